// round 11
// baseline (speedup 1.0000x reference)
#include <cuda_runtime.h>
#include <cuda_bf16.h>
#include <math.h>

#define NN   768
#define KK   32
#define CS   384
#define CZ   128
#define CG   16
#define NH   4
#define EE   (NN*KK)
#define NRBF 64

// db lookup table: d grid step 0.08, 272 points, covers d in [0, 21.68]
#define TAB_H    0.08f
#define TAB_INVH 12.5f
#define TAB_N    272
#define TAB_DMAX 21.5f

typedef unsigned long long ull;
typedef unsigned int uint;

// ---- f32x2 packed helpers (sm_100+) ----
__device__ __forceinline__ ull pk2(float lo, float hi) {
    ull r; asm("mov.b64 %0, {%1,%2};" : "=l"(r) : "f"(lo), "f"(hi)); return r;
}
__device__ __forceinline__ void upk2(ull v, float& lo, float& hi) {
    asm("mov.b64 {%0,%1}, %2;" : "=f"(lo), "=f"(hi) : "l"(v));
}
__device__ __forceinline__ ull ffma2(ull a, ull b, ull c) {
    ull d; asm("fma.rn.f32x2 %0, %1, %2, %3;" : "=l"(d) : "l"(a), "l"(b), "l"(c)); return d;
}
__device__ __forceinline__ float tanh_fast(float x) {
    float y; asm("tanh.approx.f32 %0, %1;" : "=f"(y) : "f"(x)); return y;
}
__device__ __forceinline__ __nv_bfloat162 u2b(uint u) {
    return *reinterpret_cast<__nv_bfloat162*>(&u);
}
// ---- tf32 helpers ----
__device__ __forceinline__ uint f2tf32(float x) {
    uint u; asm("cvt.rna.tf32.f32 %0, %1;" : "=r"(u) : "f"(x)); return u;
}
__device__ __forceinline__ void mma_tf32(float& d0, float& d1, float& d2, float& d3,
                                         uint a0, uint a1, uint a2, uint a3,
                                         uint b0, uint b1) {
    asm("mma.sync.aligned.m16n8k8.row.col.f32.tf32.tf32.f32 "
        "{%0,%1,%2,%3}, {%4,%5,%6,%7}, {%8,%9}, {%0,%1,%2,%3};"
        : "+f"(d0), "+f"(d1), "+f"(d2), "+f"(d3)
        : "r"(a0), "r"(a1), "r"(a2), "r"(a3), "r"(b0), "r"(b1));
}

// ---------------- scratch (device globals; allocation-free) ----------------
__device__ float g_nl[NN*CG];
__device__ float g_nr[NN*CG];
__device__ float g_z[(size_t)EE*CZ];
__device__ float g_qkvo[(size_t)EE*512];        // q[0:128) k[128:256) v[256:384) sig(og)[384:512)
__device__ float g_bias[(size_t)NN*NH*KK*KK];   // [n][h][i][j]
__device__ float g_og[(size_t)EE*CZ];
__device__ float g_wcat[CZ*512];
__device__ float g_bcat[512];
__device__ uint  g_tab[TAB_N*CZ];               // [d][c] = bf16x2(db(d*h,c), db(d*h+h,c))

// ---------------- kernel: build db lookup table ----------------
// db(d, c) = b_dist[c] + sum_{r=0}^{63} exp(-(((d - mu_r)/sigma)^2)) * wdist[r,c]
// EXACT 64-tap sum (no window truncation); one entry packs value at d and d+h.
__global__ void k_dbtab(const float* __restrict__ wdist, const float* __restrict__ b_dist)
{
    int d = blockIdx.x;     // 0..TAB_N-1
    int c = threadIdx.x;    // 0..127
    float d0 = d * TAB_H;
    float d1 = d0 + TAB_H;
    float v0 = b_dist[c], v1 = v0;
    #pragma unroll 4
    for (int r = 0; r < NRBF; r++) {
        float mu = (float)r * (20.0f/63.0f);
        float w  = __ldg(wdist + r*CZ + c);
        float x0 = (d0 - mu) * 3.2f;
        float x1 = (d1 - mu) * 3.2f;
        v0 += __expf(-x0*x0) * w;
        v1 += __expf(-x1*x1) * w;
    }
    __nv_bfloat162 p = __floats2bfloat162_rn(v0, v1);
    g_tab[d*CZ + c] = *reinterpret_cast<uint*>(&p);
}

// ---------------- kernel: concat projection weights ----------------
__global__ void k_concat(const float* __restrict__ wq, const float* __restrict__ bq,
                         const float* __restrict__ wkv, const float* __restrict__ bkv,
                         const float* __restrict__ wog, const float* __restrict__ bog)
{
    int c = blockIdx.x;
    int t = threadIdx.x;
    float v;
    if (t < 128)       v = wq[c*128 + t];
    else if (t < 384)  v = wkv[c*256 + (t-128)];
    else               v = wog[c*128 + (t-384)];
    g_wcat[c*512 + t] = v;
    if (c == 0) {
        float b;
        if (t < 128)      b = bq[t];
        else if (t < 384) b = bkv[t-128];
        else              b = bog[t-384];
        g_bcat[t] = b;
    }
}

// ---------------- kernel: node left/right projections ----------------
__global__ void k_nlr(const float* __restrict__ nf,
                      const float* __restrict__ wl, const float* __restrict__ bl,
                      const float* __restrict__ wr, const float* __restrict__ br)
{
    int n = blockIdx.x;
    int t = threadIdx.x;          // 32 threads
    int c0 = t & 15;
    const float* w = (t < 16) ? wl : wr;
    float acc = (t < 16) ? bl[c0] : br[c0];
    const float* row = nf + (size_t)n*CS;
    #pragma unroll 4
    for (int c = 0; c < CS; c++) acc += __ldg(row + c) * __ldg(w + c*CG + c0);
    if (t < 16) g_nl[n*CG + c0] = acc;
    else        g_nr[n*CG + c0] = acc;
}

// ---------------- kernel: LayerNorm over c_z ----------------
__global__ __launch_bounds__(128) void k_ln(const float* __restrict__ ef,
                                            const float* __restrict__ gam,
                                            const float* __restrict__ bet)
{
    int e = blockIdx.x;
    int t = threadIdx.x;
    float x = ef[(size_t)e*CZ + t];
    float s = x, s2 = x*x;
    #pragma unroll
    for (int o = 16; o > 0; o >>= 1) {
        s  += __shfl_xor_sync(0xffffffffu, s,  o);
        s2 += __shfl_xor_sync(0xffffffffu, s2, o);
    }
    __shared__ float ws[4], ws2[4];
    int w = t >> 5;
    if ((t & 31) == 0) { ws[w] = s; ws2[w] = s2; }
    __syncthreads();
    s  = ws[0]  + ws[1]  + ws[2]  + ws[3];
    s2 = ws2[0] + ws2[1] + ws2[2] + ws2[3];
    float mu  = s  * (1.f/128.f);
    float var = s2 * (1.f/128.f) - mu*mu;
    float inv = rsqrtf(var + 1e-5f);
    g_z[(size_t)e*CZ + t] = (x - mu) * inv * gam[t] + bet[t];
}

// ---------------- kernel: tf32 tensor-core GEMM ----------------
__global__ __launch_bounds__(256) void k_gemm_tc(const float* __restrict__ A,
                                                 const float* __restrict__ B,
                                                 float* __restrict__ C,
                                                 int ldb,
                                                 const float* __restrict__ bias,
                                                 int sigStart)
{
    __shared__ uint As[32*132];   // [k][m] tf32 bits
    __shared__ uint Bs[32*132];   // [k][n] tf32 bits
    int tid = threadIdx.x;
    int row0 = blockIdx.x * 128;
    int n0   = blockIdx.y * 128;
    int wid  = tid >> 5;
    int lane = tid & 31;
    int warp_m = wid >> 2;          // 0..1
    int warp_n = wid & 3;           // 0..3
    int gid = lane >> 2;            // 0..7
    int tig = lane & 3;             // 0..3
    int m0w = warp_m * 64;
    int n0w = warp_n * 32;

    float acc[4][4][4];
    #pragma unroll
    for (int mt = 0; mt < 4; mt++)
        #pragma unroll
        for (int nt = 0; nt < 4; nt++)
            #pragma unroll
            for (int q = 0; q < 4; q++) acc[mt][nt][q] = 0.f;

    for (int k0 = 0; k0 < 128; k0 += 32) {
        #pragma unroll
        for (int it = 0; it < 4; it++) {
            int idx = tid + it*256;
            int r = idx >> 3, kc = idx & 7;
            float4 v = *(const float4*)(A + (size_t)(row0 + r)*128 + k0 + kc*4);
            As[(kc*4+0)*132 + r] = f2tf32(v.x);
            As[(kc*4+1)*132 + r] = f2tf32(v.y);
            As[(kc*4+2)*132 + r] = f2tf32(v.z);
            As[(kc*4+3)*132 + r] = f2tf32(v.w);
        }
        #pragma unroll
        for (int it = 0; it < 4; it++) {
            int idx = tid + it*256;
            int r = idx >> 5, nc = idx & 31;
            float4 v = *(const float4*)(B + (size_t)(k0 + r)*ldb + n0 + nc*4);
            Bs[r*132 + nc*4 + 0] = f2tf32(v.x);
            Bs[r*132 + nc*4 + 1] = f2tf32(v.y);
            Bs[r*132 + nc*4 + 2] = f2tf32(v.z);
            Bs[r*132 + nc*4 + 3] = f2tf32(v.w);
        }
        __syncthreads();
        #pragma unroll
        for (int ks = 0; ks < 4; ks++) {
            int kb = ks * 8;
            const uint* a_lo = As + (kb + tig    )*132;
            const uint* a_hi = As + (kb + tig + 4)*132;
            uint af[4][4];
            #pragma unroll
            for (int mt = 0; mt < 4; mt++) {
                int ra = m0w + mt*16 + gid;
                af[mt][0] = a_lo[ra];
                af[mt][1] = a_lo[ra + 8];
                af[mt][2] = a_hi[ra];
                af[mt][3] = a_hi[ra + 8];
            }
            const uint* b_lo = Bs + (kb + tig    )*132;
            const uint* b_hi = Bs + (kb + tig + 4)*132;
            uint bf[4][2];
            #pragma unroll
            for (int nt = 0; nt < 4; nt++) {
                int cb = n0w + nt*8 + gid;
                bf[nt][0] = b_lo[cb];
                bf[nt][1] = b_hi[cb];
            }
            #pragma unroll
            for (int mt = 0; mt < 4; mt++)
                #pragma unroll
                for (int nt = 0; nt < 4; nt++)
                    mma_tf32(acc[mt][nt][0], acc[mt][nt][1], acc[mt][nt][2], acc[mt][nt][3],
                             af[mt][0], af[mt][1], af[mt][2], af[mt][3],
                             bf[nt][0], bf[nt][1]);
        }
        __syncthreads();
    }
    #pragma unroll
    for (int mt = 0; mt < 4; mt++) {
        int rowa = row0 + m0w + mt*16 + gid;
        #pragma unroll
        for (int nt = 0; nt < 4; nt++) {
            int col = n0 + n0w + nt*8 + 2*tig;
            float b0 = __ldg(bias + col), b1 = __ldg(bias + col + 1);
            float v0 = acc[mt][nt][0] + b0;
            float v1 = acc[mt][nt][1] + b1;
            float v2 = acc[mt][nt][2] + b0;
            float v3 = acc[mt][nt][3] + b1;
            if (col   >= sigStart) { v0 = __fdividef(1.f, 1.f + __expf(-v0));
                                     v2 = __fdividef(1.f, 1.f + __expf(-v2)); }
            if (col+1 >= sigStart) { v1 = __fdividef(1.f, 1.f + __expf(-v1));
                                     v3 = __fdividef(1.f, 1.f + __expf(-v3)); }
            float2 s0 = {v0, v1};
            float2 s1 = {v2, v3};
            *(float2*)(C + (size_t)rowa*ldb + col)     = s0;
            *(float2*)(C + (size_t)(rowa+8)*ldb + col) = s1;
        }
    }
}

// ---------------- kernel: triangle bias ----------------
// gate[i,j,c] = sum_k e1[i,k] * M[c,j,k],  M[c,j,k] = sum_l e2[j,l] W[k*16+l,c].
// db via PRECOMPUTED lookup table g_tab (lerp, 1 LDS.32 per (pair,c)) —
// replaces the 32B/pair/c wdist window gather that dominated smem traffic.
// bias[h,i,j] = sum_c sigm(gate)*db*wt[c,h].
__global__ __launch_bounds__(512) void k_tri(const int* __restrict__ ei,
                                             const float* __restrict__ trans,
                                             const float* __restrict__ W,       // [256,128]
                                             const float* __restrict__ b_bgate,
                                             const float* __restrict__ b_dist,
                                             const float* __restrict__ wtob)    // [128,4]
{
    __shared__ float          s_e2t[16*32];      // [l][j]                  2048B
    __shared__ float          s_t[32*4];         //                          512B
    __shared__ ull            s_wt2[128*2];      // [c][h-pair]             2048B
    __shared__ __nv_bfloat16  s_M[16*32*16];     // [c][j][k] bf16         16384B
    __shared__ uint           s_tab[TAB_N*17];   // [d][cl], stride 17     18496B
    __shared__ ull            s_bgd[128];        // pk2(bg, bd)             1024B
    __shared__ int            s_src[32];         //                          128B

    int n = blockIdx.x;
    int tid = threadIdx.x;

    if (tid < 32) s_src[tid] = ei[n*KK + tid];
    __syncthreads();
    {
        int i = tid >> 4, k = tid & 15;
        s_e2t[k*32 + i] = g_nr[s_src[i]*CG + k];
    }
    if (tid < 256) {
        int c = tid >> 1, p = tid & 1;
        s_wt2[c*2 + p] = pk2(wtob[c*4 + 2*p], wtob[c*4 + 2*p + 1]);
    }
    if (tid < 96) { int i = tid/3, c = tid - i*3; s_t[i*4+c] = trans[s_src[i]*3 + c]; }
    if (tid < 128) s_bgd[tid] = pk2(b_bgate[tid], b_dist[tid]);
    __syncthreads();

    // ---- phase B pair assignment: thread = (j, {ib, ib+1}) ----
    int j  = tid >> 4;              // 0..31
    int ib = (tid & 15) * 2;

    int   idxp[2];
    float frac[2];
    __nv_bfloat162 e1h[2][8];       // e1[i,:] pair-packed bf16
    #pragma unroll
    for (int ii = 0; ii < 2; ii++) {
        int i = ib + ii;
        float dx = s_t[i*4+0] - s_t[j*4+0] + 1e-8f;
        float dy = s_t[i*4+1] - s_t[j*4+1] + 1e-8f;
        float dz = s_t[i*4+2] - s_t[j*4+2] + 1e-8f;
        float dd = sqrtf(dx*dx + dy*dy + dz*dz);
        dd = fminf(dd, TAB_DMAX);
        float u = dd * TAB_INVH;
        int idx = (int)u;
        idxp[ii] = idx;
        frac[ii] = u - (float)idx;
        const float4* ep = (const float4*)(g_nl + s_src[i]*CG);
        #pragma unroll
        for (int q = 0; q < 4; q++) {
            float4 e4 = __ldg(ep + q);
            e1h[ii][2*q  ] = __floats2bfloat162_rn(e4.x, e4.y);
            e1h[ii][2*q+1] = __floats2bfloat162_rn(e4.z, e4.w);
        }
    }

    // ---- phase A assignment: jA warp-spread, kA = lane&15 for coalesced STS
    int jA = tid >> 4;              // 0..31 (2 per warp)
    int kA = tid & 15;              // 0..15

    ull bacc[2][2] = {{0ull, 0ull}, {0ull, 0ull}};   // [ii][h-pair], f32x2

    for (int ch = 0; ch < 8; ch++) {
        int cb = ch * 16;
        // stage db-table slice: s_tab[d*17 + cl] = g_tab[d*128 + cb + cl]
        for (int p = tid; p < TAB_N*16; p += 512) {
            int d = p >> 4, cl = p & 15;
            s_tab[d*17 + cl] = __ldg(g_tab + d*CZ + cb + cl);
        }
        // phase A: M[c][j][k] = sum_l e2[j,l] * W[(k*16+l)*128 + cb+c]
        {
            ull a2[8];
            #pragma unroll
            for (int c2 = 0; c2 < 8; c2++) a2[c2] = 0ull;
            #pragma unroll
            for (int l = 0; l < 16; l++) {
                float e2v = s_e2t[l*32 + jA];
                ull e2p = pk2(e2v, e2v);
                const ulonglong2* Wp = (const ulonglong2*)(W + (size_t)(kA*16 + l)*128 + cb);
                ulonglong2 w01 = __ldg(Wp+0), w23 = __ldg(Wp+1), w45 = __ldg(Wp+2), w67 = __ldg(Wp+3);
                a2[0] = ffma2(e2p, w01.x, a2[0]); a2[1] = ffma2(e2p, w01.y, a2[1]);
                a2[2] = ffma2(e2p, w23.x, a2[2]); a2[3] = ffma2(e2p, w23.y, a2[3]);
                a2[4] = ffma2(e2p, w45.x, a2[4]); a2[5] = ffma2(e2p, w45.y, a2[5]);
                a2[6] = ffma2(e2p, w67.x, a2[6]); a2[7] = ffma2(e2p, w67.y, a2[7]);
            }
            #pragma unroll
            for (int c2 = 0; c2 < 8; c2++) {
                float lo, hi;
                upk2(a2[c2], lo, hi);
                s_M[((2*c2  )*32 + jA)*16 + kA] = __float2bfloat16_rn(lo);
                s_M[((2*c2+1)*32 + jA)*16 + kA] = __float2bfloat16_rn(hi);
            }
        }
        __syncthreads();
        // phase B
        #pragma unroll 1
        for (int cc = 0; cc < 16; cc++) {
            int c = cb + cc;
            const __nv_bfloat16* mrow = s_M + (cc*32 + j)*16;   // 32B row, broadcast-ish
            uint4 ma = *(const uint4*)(mrow);
            uint4 mb = *(const uint4*)(mrow + 8);
            float bg, bd_unused;
            upk2(s_bgd[c], bg, bd_unused);
            float t01[2];
            #pragma unroll
            for (int ii = 0; ii < 2; ii++) {
                __nv_bfloat162 ga = __floats2bfloat162_rn(0.f, 0.f);
                ga = __hfma2(e1h[ii][0], u2b(ma.x), ga);
                ga = __hfma2(e1h[ii][1], u2b(ma.y), ga);
                ga = __hfma2(e1h[ii][2], u2b(ma.z), ga);
                ga = __hfma2(e1h[ii][3], u2b(ma.w), ga);
                ga = __hfma2(e1h[ii][4], u2b(mb.x), ga);
                ga = __hfma2(e1h[ii][5], u2b(mb.y), ga);
                ga = __hfma2(e1h[ii][6], u2b(mb.z), ga);
                ga = __hfma2(e1h[ii][7], u2b(mb.w), ga);
                float g = __low2float(ga) + __high2float(ga) + bg;
                float sg = 0.5f + 0.5f*tanh_fast(0.5f*g);
                // db: one LDS.32 -> (db(idx), db(idx+1)) bf16x2, lerp in f32
                uint tv = s_tab[idxp[ii]*17 + cc];
                float2 t2 = __bfloat1622float2(u2b(tv));
                float db = t2.x + frac[ii]*(t2.y - t2.x);
                t01[ii] = sg * db;
            }
            const ull* wt = s_wt2 + c*2;
            ull wt0 = wt[0], wt1 = wt[1];
            ull tp0 = pk2(t01[0], t01[0]);
            ull tp1 = pk2(t01[1], t01[1]);
            bacc[0][0] = ffma2(tp0, wt0, bacc[0][0]);
            bacc[0][1] = ffma2(tp0, wt1, bacc[0][1]);
            bacc[1][0] = ffma2(tp1, wt0, bacc[1][0]);
            bacc[1][1] = ffma2(tp1, wt1, bacc[1][1]);
        }
        __syncthreads();
    }
    #pragma unroll
    for (int ii = 0; ii < 2; ii++) {
        int i = ib + ii;
        float b0, b1, b2, b3;
        upk2(bacc[ii][0], b0, b1);
        upk2(bacc[ii][1], b2, b3);
        g_bias[(((size_t)n*NH + 0)*KK + i)*KK + j] = b0;
        g_bias[(((size_t)n*NH + 1)*KK + i)*KK + j] = b1;
        g_bias[(((size_t)n*NH + 2)*KK + i)*KK + j] = b2;
        g_bias[(((size_t)n*NH + 3)*KK + i)*KK + j] = b3;
    }
}

// ---------------- kernel: attention over K neighbors, per node ----------------
__global__ __launch_bounds__(128) void k_attn()
{
    int n = blockIdx.x;
    int tid = threadIdx.x;
    int h = tid >> 5, i = tid & 31;
    __shared__ float sk[KK*CZ];
    __shared__ float sv[KK*CZ];
    for (int p = tid; p < KK*CZ; p += 128) {
        int jj = p >> 7, c = p & 127;
        size_t base = (size_t)(n*KK + jj) * 512;
        sk[p] = g_qkvo[base + 128 + c];
        sv[p] = g_qkvo[base + 256 + c];
    }
    float qr[32];
    const float scale = 0.17677669529663687f;   // 1/sqrt(32)
    size_t erow = (size_t)(n*KK + i) * 512;
    #pragma unroll
    for (int d = 0; d < 32; d++) qr[d] = g_qkvo[erow + h*32 + d] * scale;
    __syncthreads();

    float s[32];
    float mx = -1e30f;
    const float* bp = g_bias + (((size_t)n*NH + h)*KK + i)*KK;
    #pragma unroll
    for (int jj = 0; jj < 32; jj++) {
        float acc = bp[jj];
        const float* kp = sk + jj*128 + h*32;
        #pragma unroll
        for (int d = 0; d < 32; d++) acc += qr[d] * kp[d];
        s[jj] = acc;
        mx = fmaxf(mx, acc);
    }
    float sum = 0.f;
    #pragma unroll
    for (int jj = 0; jj < 32; jj++) { s[jj] = __expf(s[jj] - mx); sum += s[jj]; }
    float inv = __fdividef(1.f, sum);
    float* op = g_og + (size_t)(n*KK + i)*CZ + h*32;
    const float* ogp = g_qkvo + erow + 384 + h*32;
    #pragma unroll
    for (int d = 0; d < 32; d++) {
        float acc = 0.f;
        const float* vp = sv + h*32 + d;
        #pragma unroll
        for (int jj = 0; jj < 32; jj++) acc += s[jj] * vp[jj*128];
        op[d] = acc * inv * ogp[d];
    }
}

// ---------------- launch ----------------
extern "C" void kernel_launch(void* const* d_in, const int* in_sizes, int n_in,
                              void* d_out, int out_size)
{
    const float* nf       = (const float*)d_in[0];
    const float* trans    = (const float*)d_in[1];
    const float* ef       = (const float*)d_in[2];
    const int*   ei       = (const int*)d_in[3];
    const float* w_left   = (const float*)d_in[4];
    const float* b_left   = (const float*)d_in[5];
    const float* w_right  = (const float*)d_in[6];
    const float* b_right  = (const float*)d_in[7];
    const float* w_bgate  = (const float*)d_in[8];
    const float* b_bgate  = (const float*)d_in[9];
    const float* w_dist   = (const float*)d_in[10];
    const float* b_dist   = (const float*)d_in[11];
    const float* w_tobias = (const float*)d_in[12];
    const float* ln_g     = (const float*)d_in[13];
    const float* ln_b     = (const float*)d_in[14];
    const float* w_q      = (const float*)d_in[15];
    const float* b_q      = (const float*)d_in[16];
    const float* w_kv     = (const float*)d_in[17];
    const float* b_kv     = (const float*)d_in[18];
    const float* w_out    = (const float*)d_in[19];
    const float* b_out    = (const float*)d_in[20];
    const float* w_ogate  = (const float*)d_in[21];
    const float* b_ogate  = (const float*)d_in[22];
    float* out = (float*)d_out;

    float *p_z, *p_qkvo, *p_og, *p_wcat, *p_bcat;
    cudaGetSymbolAddress((void**)&p_z,    g_z);
    cudaGetSymbolAddress((void**)&p_qkvo, g_qkvo);
    cudaGetSymbolAddress((void**)&p_og,   g_og);
    cudaGetSymbolAddress((void**)&p_wcat, g_wcat);
    cudaGetSymbolAddress((void**)&p_bcat, g_bcat);

    k_dbtab<<<TAB_N, 128>>>(w_dist, b_dist);
    k_concat<<<128, 512>>>(w_q, b_q, w_kv, b_kv, w_ogate, b_ogate);
    k_nlr<<<NN, 32>>>(nf, w_left, b_left, w_right, b_right);
    k_ln<<<EE, 128>>>(ef, ln_g, ln_b);
    k_tri<<<NN, 512>>>(ei, trans, w_bgate, b_bgate, b_dist, w_tobias);
    {
        dim3 g(EE/128, 512/128);
        k_gemm_tc<<<g, 256>>>(p_z, p_wcat, p_qkvo, 512, p_bcat, 384);
    }
    k_attn<<<NN, 128>>>();
    {
        dim3 g(EE/128, 1);
        k_gemm_tc<<<g, 256>>>(p_og, w_out, out, 128, b_out, 1 << 30);
    }
}

// round 14
// speedup vs baseline: 2.0752x; 2.0752x over previous
#include <cuda_runtime.h>
#include <cuda_bf16.h>
#include <math.h>

#define NN   768
#define KK   32
#define CS   384
#define CZ   128
#define CG   16
#define NH   4
#define EE   (NN*KK)
#define NRBF 64

// db lookup table: d grid step 0.08, 272 points, covers d in [0, 21.68]
#define TAB_H    0.08f
#define TAB_INVH 12.5f
#define TAB_N    272
#define TAB_DMAX 21.5f

typedef unsigned long long ull;
typedef unsigned int uint;

// ---- f32x2 packed helpers (sm_100+) ----
__device__ __forceinline__ ull pk2(float lo, float hi) {
    ull r; asm("mov.b64 %0, {%1,%2};" : "=l"(r) : "f"(lo), "f"(hi)); return r;
}
__device__ __forceinline__ void upk2(ull v, float& lo, float& hi) {
    asm("mov.b64 {%0,%1}, %2;" : "=f"(lo), "=f"(hi) : "l"(v));
}
__device__ __forceinline__ ull ffma2(ull a, ull b, ull c) {
    ull d; asm("fma.rn.f32x2 %0, %1, %2, %3;" : "=l"(d) : "l"(a), "l"(b), "l"(c)); return d;
}
__device__ __forceinline__ float tanh_fast(float x) {
    float y; asm("tanh.approx.f32 %0, %1;" : "=f"(y) : "f"(x)); return y;
}
__device__ __forceinline__ __nv_bfloat162 u2b(uint u) {
    return *reinterpret_cast<__nv_bfloat162*>(&u);
}
// ---- tf32 helpers ----
__device__ __forceinline__ uint f2tf32(float x) {
    uint u; asm("cvt.rna.tf32.f32 %0, %1;" : "=r"(u) : "f"(x)); return u;
}
__device__ __forceinline__ void mma_tf32(float& d0, float& d1, float& d2, float& d3,
                                         uint a0, uint a1, uint a2, uint a3,
                                         uint b0, uint b1) {
    asm("mma.sync.aligned.m16n8k8.row.col.f32.tf32.tf32.f32 "
        "{%0,%1,%2,%3}, {%4,%5,%6,%7}, {%8,%9}, {%0,%1,%2,%3};"
        : "+f"(d0), "+f"(d1), "+f"(d2), "+f"(d3)
        : "r"(a0), "r"(a1), "r"(a2), "r"(a3), "r"(b0), "r"(b1));
}

// ---------------- scratch (device globals; allocation-free) ----------------
__device__ float g_nl[NN*CG];
__device__ float g_nr[NN*CG];
__device__ float g_z[(size_t)EE*CZ];
__device__ float g_qkvo[(size_t)EE*512];        // q[0:128) k[128:256) v[256:384) sig(og)[384:512)
__device__ float g_bias[(size_t)NN*NH*KK*KK];   // [n][h][i][j]
__device__ float g_og[(size_t)EE*CZ];
__device__ float g_wcat[CZ*512];
__device__ float g_bcat[512];
__device__ uint  g_tab[TAB_N*CZ];               // [d][c] = bf16x2(db(d*h,c), db(d*h+h,c))

// ---------------- kernel: build db lookup table ----------------
// db(d, c) = b_dist[c] + sum_r exp(-(((d - mu_r)/sigma)^2)) * wdist[r,c]
// EXACT 64-tap sum; entry packs values at d and d+h for one-load lerp.
__global__ void k_dbtab(const float* __restrict__ wdist, const float* __restrict__ b_dist)
{
    int d = blockIdx.x;     // 0..TAB_N-1
    int c = threadIdx.x;    // 0..127
    float d0 = d * TAB_H;
    float d1 = d0 + TAB_H;
    float v0 = b_dist[c], v1 = v0;
    #pragma unroll 4
    for (int r = 0; r < NRBF; r++) {
        float mu = (float)r * (20.0f/63.0f);
        float w  = __ldg(wdist + r*CZ + c);
        float x0 = (d0 - mu) * 3.2f;
        float x1 = (d1 - mu) * 3.2f;
        v0 += __expf(-x0*x0) * w;
        v1 += __expf(-x1*x1) * w;
    }
    __nv_bfloat162 p = __floats2bfloat162_rn(v0, v1);
    g_tab[d*CZ + c] = *reinterpret_cast<uint*>(&p);
}

// ---------------- kernel: concat projection weights ----------------
__global__ void k_concat(const float* __restrict__ wq, const float* __restrict__ bq,
                         const float* __restrict__ wkv, const float* __restrict__ bkv,
                         const float* __restrict__ wog, const float* __restrict__ bog)
{
    int c = blockIdx.x;
    int t = threadIdx.x;
    float v;
    if (t < 128)       v = wq[c*128 + t];
    else if (t < 384)  v = wkv[c*256 + (t-128)];
    else               v = wog[c*128 + (t-384)];
    g_wcat[c*512 + t] = v;
    if (c == 0) {
        float b;
        if (t < 128)      b = bq[t];
        else if (t < 384) b = bkv[t-128];
        else              b = bog[t-384];
        g_bcat[t] = b;
    }
}

// ---------------- kernel: node left/right projections ----------------
__global__ void k_nlr(const float* __restrict__ nf,
                      const float* __restrict__ wl, const float* __restrict__ bl,
                      const float* __restrict__ wr, const float* __restrict__ br)
{
    int n = blockIdx.x;
    int t = threadIdx.x;          // 32 threads
    int c0 = t & 15;
    const float* w = (t < 16) ? wl : wr;
    float acc = (t < 16) ? bl[c0] : br[c0];
    const float* row = nf + (size_t)n*CS;
    #pragma unroll 4
    for (int c = 0; c < CS; c++) acc += __ldg(row + c) * __ldg(w + c*CG + c0);
    if (t < 16) g_nl[n*CG + c0] = acc;
    else        g_nr[n*CG + c0] = acc;
}

// ---------------- kernel: LayerNorm over c_z ----------------
__global__ __launch_bounds__(128) void k_ln(const float* __restrict__ ef,
                                            const float* __restrict__ gam,
                                            const float* __restrict__ bet)
{
    int e = blockIdx.x;
    int t = threadIdx.x;
    float x = ef[(size_t)e*CZ + t];
    float s = x, s2 = x*x;
    #pragma unroll
    for (int o = 16; o > 0; o >>= 1) {
        s  += __shfl_xor_sync(0xffffffffu, s,  o);
        s2 += __shfl_xor_sync(0xffffffffu, s2, o);
    }
    __shared__ float ws[4], ws2[4];
    int w = t >> 5;
    if ((t & 31) == 0) { ws[w] = s; ws2[w] = s2; }
    __syncthreads();
    s  = ws[0]  + ws[1]  + ws[2]  + ws[3];
    s2 = ws2[0] + ws2[1] + ws2[2] + ws2[3];
    float mu  = s  * (1.f/128.f);
    float var = s2 * (1.f/128.f) - mu*mu;
    float inv = rsqrtf(var + 1e-5f);
    g_z[(size_t)e*CZ + t] = (x - mu) * inv * gam[t] + bet[t];
}

// ---------------- kernel: tf32 tensor-core GEMM ----------------
__global__ __launch_bounds__(256) void k_gemm_tc(const float* __restrict__ A,
                                                 const float* __restrict__ B,
                                                 float* __restrict__ C,
                                                 int ldb,
                                                 const float* __restrict__ bias,
                                                 int sigStart)
{
    __shared__ uint As[32*132];   // [k][m] tf32 bits
    __shared__ uint Bs[32*132];   // [k][n] tf32 bits
    int tid = threadIdx.x;
    int row0 = blockIdx.x * 128;
    int n0   = blockIdx.y * 128;
    int wid  = tid >> 5;
    int lane = tid & 31;
    int warp_m = wid >> 2;          // 0..1
    int warp_n = wid & 3;           // 0..3
    int gid = lane >> 2;            // 0..7
    int tig = lane & 3;             // 0..3
    int m0w = warp_m * 64;
    int n0w = warp_n * 32;

    float acc[4][4][4];
    #pragma unroll
    for (int mt = 0; mt < 4; mt++)
        #pragma unroll
        for (int nt = 0; nt < 4; nt++)
            #pragma unroll
            for (int q = 0; q < 4; q++) acc[mt][nt][q] = 0.f;

    for (int k0 = 0; k0 < 128; k0 += 32) {
        #pragma unroll
        for (int it = 0; it < 4; it++) {
            int idx = tid + it*256;
            int r = idx >> 3, kc = idx & 7;
            float4 v = *(const float4*)(A + (size_t)(row0 + r)*128 + k0 + kc*4);
            As[(kc*4+0)*132 + r] = f2tf32(v.x);
            As[(kc*4+1)*132 + r] = f2tf32(v.y);
            As[(kc*4+2)*132 + r] = f2tf32(v.z);
            As[(kc*4+3)*132 + r] = f2tf32(v.w);
        }
        #pragma unroll
        for (int it = 0; it < 4; it++) {
            int idx = tid + it*256;
            int r = idx >> 5, nc = idx & 31;
            float4 v = *(const float4*)(B + (size_t)(k0 + r)*ldb + n0 + nc*4);
            Bs[r*132 + nc*4 + 0] = f2tf32(v.x);
            Bs[r*132 + nc*4 + 1] = f2tf32(v.y);
            Bs[r*132 + nc*4 + 2] = f2tf32(v.z);
            Bs[r*132 + nc*4 + 3] = f2tf32(v.w);
        }
        __syncthreads();
        #pragma unroll
        for (int ks = 0; ks < 4; ks++) {
            int kb = ks * 8;
            const uint* a_lo = As + (kb + tig    )*132;
            const uint* a_hi = As + (kb + tig + 4)*132;
            uint af[4][4];
            #pragma unroll
            for (int mt = 0; mt < 4; mt++) {
                int ra = m0w + mt*16 + gid;
                af[mt][0] = a_lo[ra];
                af[mt][1] = a_lo[ra + 8];
                af[mt][2] = a_hi[ra];
                af[mt][3] = a_hi[ra + 8];
            }
            const uint* b_lo = Bs + (kb + tig    )*132;
            const uint* b_hi = Bs + (kb + tig + 4)*132;
            uint bf[4][2];
            #pragma unroll
            for (int nt = 0; nt < 4; nt++) {
                int cb = n0w + nt*8 + gid;
                bf[nt][0] = b_lo[cb];
                bf[nt][1] = b_hi[cb];
            }
            #pragma unroll
            for (int mt = 0; mt < 4; mt++)
                #pragma unroll
                for (int nt = 0; nt < 4; nt++)
                    mma_tf32(acc[mt][nt][0], acc[mt][nt][1], acc[mt][nt][2], acc[mt][nt][3],
                             af[mt][0], af[mt][1], af[mt][2], af[mt][3],
                             bf[nt][0], bf[nt][1]);
        }
        __syncthreads();
    }
    #pragma unroll
    for (int mt = 0; mt < 4; mt++) {
        int rowa = row0 + m0w + mt*16 + gid;
        #pragma unroll
        for (int nt = 0; nt < 4; nt++) {
            int col = n0 + n0w + nt*8 + 2*tig;
            float b0 = __ldg(bias + col), b1 = __ldg(bias + col + 1);
            float v0 = acc[mt][nt][0] + b0;
            float v1 = acc[mt][nt][1] + b1;
            float v2 = acc[mt][nt][2] + b0;
            float v3 = acc[mt][nt][3] + b1;
            if (col   >= sigStart) { v0 = __fdividef(1.f, 1.f + __expf(-v0));
                                     v2 = __fdividef(1.f, 1.f + __expf(-v2)); }
            if (col+1 >= sigStart) { v1 = __fdividef(1.f, 1.f + __expf(-v1));
                                     v3 = __fdividef(1.f, 1.f + __expf(-v3)); }
            float2 s0 = {v0, v1};
            float2 s1 = {v2, v3};
            *(float2*)(C + (size_t)rowa*ldb + col)     = s0;
            *(float2*)(C + (size_t)(rowa+8)*ldb + col) = s1;
        }
    }
}

// ---------------- kernel: triangle bias ----------------
// gate[i,j,c] = sum_k e1[i,k] * M[c,j,k],  M[c,j,k] = sum_l e2[j,l] W[k*16+l,c].
// Phase A: kA WARP-UNIFORM -> W loads are 1-sector broadcasts (R11's remap to
// per-lane kA caused 16x LDG sector traffic and the 2x regression).
// db via precomputed table; smem slice strided 20 uints so each thread pulls
// 4 channels per LDS.128 (idx*80B is 16B-aligned).
__global__ __launch_bounds__(512) void k_tri(const int* __restrict__ ei,
                                             const float* __restrict__ trans,
                                             const float* __restrict__ W,       // [256,128]
                                             const float* __restrict__ b_bgate,
                                             const float* __restrict__ wtob)    // [128,4]
{
    __shared__ float          s_e2t[16*32];      // [l][j]                  2048B
    __shared__ float          s_t[32*4];         //                          512B
    __shared__ ull            s_wt2[128*2];      // [c][h-pair]             2048B
    __shared__ __nv_bfloat16  s_M[16*32*16];     // [c][j][k] bf16         16384B
    __shared__ uint           s_tab[TAB_N*20];   // [d][cl], stride 20     21760B
    __shared__ float          s_bg[128];         //                          512B
    __shared__ int            s_src[32];         //                          128B

    int n = blockIdx.x;
    int tid = threadIdx.x;

    if (tid < 32) s_src[tid] = ei[n*KK + tid];
    __syncthreads();
    {
        int i = tid >> 4, k = tid & 15;
        s_e2t[k*32 + i] = g_nr[s_src[i]*CG + k];
    }
    if (tid < 256) {
        int c = tid >> 1, p = tid & 1;
        s_wt2[c*2 + p] = pk2(wtob[c*4 + 2*p], wtob[c*4 + 2*p + 1]);
    }
    if (tid < 96) { int i = tid/3, c = tid - i*3; s_t[i*4+c] = trans[s_src[i]*3 + c]; }
    if (tid < 128) s_bg[tid] = b_bgate[tid];
    __syncthreads();

    // ---- phase B pair assignment: thread = (j, {ib, ib+1}) ----
    int j  = tid >> 4;              // 0..31
    int ib = (tid & 15) * 2;

    int   idxp[2];
    float frac[2];
    __nv_bfloat162 e1h[2][8];       // e1[i,:] pair-packed bf16
    #pragma unroll
    for (int ii = 0; ii < 2; ii++) {
        int i = ib + ii;
        float dx = s_t[i*4+0] - s_t[j*4+0] + 1e-8f;
        float dy = s_t[i*4+1] - s_t[j*4+1] + 1e-8f;
        float dz = s_t[i*4+2] - s_t[j*4+2] + 1e-8f;
        float dd = sqrtf(dx*dx + dy*dy + dz*dz);
        dd = fminf(dd, TAB_DMAX);
        float u = dd * TAB_INVH;
        int idx = (int)u;
        idxp[ii] = idx;
        frac[ii] = u - (float)idx;
        const float4* ep = (const float4*)(g_nl + s_src[i]*CG);
        #pragma unroll
        for (int q = 0; q < 4; q++) {
            float4 e4 = __ldg(ep + q);
            e1h[ii][2*q  ] = __floats2bfloat162_rn(e4.x, e4.y);
            e1h[ii][2*q+1] = __floats2bfloat162_rn(e4.z, e4.w);
        }
    }

    // ---- phase A assignment: jA = lane, kA WARP-UNIFORM -> W broadcasts ----
    int jA = tid & 31;
    int kA = tid >> 5;

    ull bacc[2][2] = {{0ull, 0ull}, {0ull, 0ull}};   // [ii][h-pair], f32x2

    for (int ch = 0; ch < 8; ch++) {
        int cb = ch * 16;
        // stage db-table slice: s_tab[d*20 + cl] = g_tab[d*128 + cb + cl]
        for (int p = tid; p < TAB_N*16; p += 512) {
            int d = p >> 4, cl = p & 15;
            s_tab[d*20 + cl] = __ldg(g_tab + d*CZ + cb + cl);
        }
        // phase A: M[c][j][k] = sum_l e2[j,l] * W[(k*16+l)*128 + cb+c]
        {
            ull a2[8];
            #pragma unroll
            for (int c2 = 0; c2 < 8; c2++) a2[c2] = 0ull;
            #pragma unroll
            for (int l = 0; l < 16; l++) {
                float e2v = s_e2t[l*32 + jA];
                ull e2p = pk2(e2v, e2v);
                const ulonglong2* Wp = (const ulonglong2*)(W + (size_t)(kA*16 + l)*128 + cb);
                ulonglong2 w01 = __ldg(Wp+0), w23 = __ldg(Wp+1), w45 = __ldg(Wp+2), w67 = __ldg(Wp+3);
                a2[0] = ffma2(e2p, w01.x, a2[0]); a2[1] = ffma2(e2p, w01.y, a2[1]);
                a2[2] = ffma2(e2p, w23.x, a2[2]); a2[3] = ffma2(e2p, w23.y, a2[3]);
                a2[4] = ffma2(e2p, w45.x, a2[4]); a2[5] = ffma2(e2p, w45.y, a2[5]);
                a2[6] = ffma2(e2p, w67.x, a2[6]); a2[7] = ffma2(e2p, w67.y, a2[7]);
            }
            #pragma unroll
            for (int c2 = 0; c2 < 8; c2++) {
                float lo, hi;
                upk2(a2[c2], lo, hi);
                s_M[((2*c2  )*32 + jA)*16 + kA] = __float2bfloat16_rn(lo);
                s_M[((2*c2+1)*32 + jA)*16 + kA] = __float2bfloat16_rn(hi);
            }
        }
        __syncthreads();
        // phase B: 4 channel-quads; one LDS.128 per (ii, quad) covers 4 channels
        #pragma unroll 1
        for (int q4 = 0; q4 < 4; q4++) {
            uint4 tq0 = *(const uint4*)(s_tab + idxp[0]*20 + q4*4);
            uint4 tq1 = *(const uint4*)(s_tab + idxp[1]*20 + q4*4);
            uint ta0[4] = {tq0.x, tq0.y, tq0.z, tq0.w};
            uint ta1[4] = {tq1.x, tq1.y, tq1.z, tq1.w};
            #pragma unroll
            for (int c2 = 0; c2 < 4; c2++) {
                int cc = q4*4 + c2;
                int c = cb + cc;
                const __nv_bfloat16* mrow = s_M + (cc*32 + j)*16;   // broadcast (j warp-uniform)
                uint4 ma = *(const uint4*)(mrow);
                uint4 mb = *(const uint4*)(mrow + 8);
                float bg = s_bg[c];
                float t01[2];
                #pragma unroll
                for (int ii = 0; ii < 2; ii++) {
                    __nv_bfloat162 ga = __floats2bfloat162_rn(0.f, 0.f);
                    ga = __hfma2(e1h[ii][0], u2b(ma.x), ga);
                    ga = __hfma2(e1h[ii][1], u2b(ma.y), ga);
                    ga = __hfma2(e1h[ii][2], u2b(ma.z), ga);
                    ga = __hfma2(e1h[ii][3], u2b(ma.w), ga);
                    ga = __hfma2(e1h[ii][4], u2b(mb.x), ga);
                    ga = __hfma2(e1h[ii][5], u2b(mb.y), ga);
                    ga = __hfma2(e1h[ii][6], u2b(mb.z), ga);
                    ga = __hfma2(e1h[ii][7], u2b(mb.w), ga);
                    float g = __low2float(ga) + __high2float(ga) + bg;
                    float sg = 0.5f + 0.5f*tanh_fast(0.5f*g);
                    uint tv = (ii == 0) ? ta0[c2] : ta1[c2];
                    float2 t2 = __bfloat1622float2(u2b(tv));
                    float db = t2.x + frac[ii]*(t2.y - t2.x);
                    t01[ii] = sg * db;
                }
                const ull* wt = s_wt2 + c*2;
                ull wt0 = wt[0], wt1 = wt[1];
                ull tp0 = pk2(t01[0], t01[0]);
                ull tp1 = pk2(t01[1], t01[1]);
                bacc[0][0] = ffma2(tp0, wt0, bacc[0][0]);
                bacc[0][1] = ffma2(tp0, wt1, bacc[0][1]);
                bacc[1][0] = ffma2(tp1, wt0, bacc[1][0]);
                bacc[1][1] = ffma2(tp1, wt1, bacc[1][1]);
            }
        }
        __syncthreads();
    }
    #pragma unroll
    for (int ii = 0; ii < 2; ii++) {
        int i = ib + ii;
        float b0, b1, b2, b3;
        upk2(bacc[ii][0], b0, b1);
        upk2(bacc[ii][1], b2, b3);
        g_bias[(((size_t)n*NH + 0)*KK + i)*KK + j] = b0;
        g_bias[(((size_t)n*NH + 1)*KK + i)*KK + j] = b1;
        g_bias[(((size_t)n*NH + 2)*KK + i)*KK + j] = b2;
        g_bias[(((size_t)n*NH + 3)*KK + i)*KK + j] = b3;
    }
}

// ---------------- kernel: attention over K neighbors, per node ----------------
__global__ __launch_bounds__(128) void k_attn()
{
    int n = blockIdx.x;
    int tid = threadIdx.x;
    int h = tid >> 5, i = tid & 31;
    __shared__ float sk[KK*CZ];
    __shared__ float sv[KK*CZ];
    for (int p = tid; p < KK*CZ; p += 128) {
        int jj = p >> 7, c = p & 127;
        size_t base = (size_t)(n*KK + jj) * 512;
        sk[p] = g_qkvo[base + 128 + c];
        sv[p] = g_qkvo[base + 256 + c];
    }
    float qr[32];
    const float scale = 0.17677669529663687f;   // 1/sqrt(32)
    size_t erow = (size_t)(n*KK + i) * 512;
    #pragma unroll
    for (int d = 0; d < 32; d++) qr[d] = g_qkvo[erow + h*32 + d] * scale;
    __syncthreads();

    float s[32];
    float mx = -1e30f;
    const float* bp = g_bias + (((size_t)n*NH + h)*KK + i)*KK;
    #pragma unroll
    for (int jj = 0; jj < 32; jj++) {
        float acc = bp[jj];
        const float* kp = sk + jj*128 + h*32;
        #pragma unroll
        for (int d = 0; d < 32; d++) acc += qr[d] * kp[d];
        s[jj] = acc;
        mx = fmaxf(mx, acc);
    }
    float sum = 0.f;
    #pragma unroll
    for (int jj = 0; jj < 32; jj++) { s[jj] = __expf(s[jj] - mx); sum += s[jj]; }
    float inv = __fdividef(1.f, sum);
    float* op = g_og + (size_t)(n*KK + i)*CZ + h*32;
    const float* ogp = g_qkvo + erow + 384 + h*32;
    #pragma unroll
    for (int d = 0; d < 32; d++) {
        float acc = 0.f;
        const float* vp = sv + h*32 + d;
        #pragma unroll
        for (int jj = 0; jj < 32; jj++) acc += s[jj] * vp[jj*128];
        op[d] = acc * inv * ogp[d];
    }
}

// ---------------- launch ----------------
extern "C" void kernel_launch(void* const* d_in, const int* in_sizes, int n_in,
                              void* d_out, int out_size)
{
    const float* nf       = (const float*)d_in[0];
    const float* trans    = (const float*)d_in[1];
    const float* ef       = (const float*)d_in[2];
    const int*   ei       = (const int*)d_in[3];
    const float* w_left   = (const float*)d_in[4];
    const float* b_left   = (const float*)d_in[5];
    const float* w_right  = (const float*)d_in[6];
    const float* b_right  = (const float*)d_in[7];
    const float* w_bgate  = (const float*)d_in[8];
    const float* b_bgate  = (const float*)d_in[9];
    const float* w_dist   = (const float*)d_in[10];
    const float* b_dist   = (const float*)d_in[11];
    const float* w_tobias = (const float*)d_in[12];
    const float* ln_g     = (const float*)d_in[13];
    const float* ln_b     = (const float*)d_in[14];
    const float* w_q      = (const float*)d_in[15];
    const float* b_q      = (const float*)d_in[16];
    const float* w_kv     = (const float*)d_in[17];
    const float* b_kv     = (const float*)d_in[18];
    const float* w_out    = (const float*)d_in[19];
    const float* b_out    = (const float*)d_in[20];
    const float* w_ogate  = (const float*)d_in[21];
    const float* b_ogate  = (const float*)d_in[22];
    float* out = (float*)d_out;

    float *p_z, *p_qkvo, *p_og, *p_wcat, *p_bcat;
    cudaGetSymbolAddress((void**)&p_z,    g_z);
    cudaGetSymbolAddress((void**)&p_qkvo, g_qkvo);
    cudaGetSymbolAddress((void**)&p_og,   g_og);
    cudaGetSymbolAddress((void**)&p_wcat, g_wcat);
    cudaGetSymbolAddress((void**)&p_bcat, g_bcat);

    // k_tri is launch #4 (ncu -s 5 -c 1 capture slot); legal since k_tri
    // does not depend on k_ln.
    k_concat<<<128, 512>>>(w_q, b_q, w_kv, b_kv, w_ogate, b_ogate);
    k_dbtab<<<TAB_N, 128>>>(w_dist, b_dist);
    k_nlr<<<NN, 32>>>(nf, w_left, b_left, w_right, b_right);
    k_tri<<<NN, 512>>>(ei, trans, w_bgate, b_bgate, w_tobias);
    k_ln<<<EE, 128>>>(ef, ln_g, ln_b);
    {
        dim3 g(EE/128, 512/128);
        k_gemm_tc<<<g, 256>>>(p_z, p_wcat, p_qkvo, 512, p_bcat, 384);
    }
    k_attn<<<NN, 128>>>();
    {
        dim3 g(EE/128, 1);
        k_gemm_tc<<<g, 256>>>(p_og, w_out, out, 128, b_out, 1 << 30);
    }
}

// round 15
// speedup vs baseline: 2.3262x; 1.1209x over previous
#include <cuda_runtime.h>
#include <cuda_bf16.h>
#include <math.h>

#define NN   768
#define KK   32
#define CS   384
#define CZ   128
#define CG   16
#define NH   4
#define EE   (NN*KK)
#define NRBF 64

// db lookup table: d grid step 0.08, 272 points, covers d in [0, 21.68]
#define TAB_H    0.08f
#define TAB_INVH 12.5f
#define TAB_N    272
#define TAB_DMAX 21.5f

typedef unsigned long long ull;
typedef unsigned int uint;

// ---- f32x2 packed helpers (sm_100+) ----
__device__ __forceinline__ ull pk2(float lo, float hi) {
    ull r; asm("mov.b64 %0, {%1,%2};" : "=l"(r) : "f"(lo), "f"(hi)); return r;
}
__device__ __forceinline__ void upk2(ull v, float& lo, float& hi) {
    asm("mov.b64 {%0,%1}, %2;" : "=f"(lo), "=f"(hi) : "l"(v));
}
__device__ __forceinline__ ull ffma2(ull a, ull b, ull c) {
    ull d; asm("fma.rn.f32x2 %0, %1, %2, %3;" : "=l"(d) : "l"(a), "l"(b), "l"(c)); return d;
}
__device__ __forceinline__ float tanh_fast(float x) {
    float y; asm("tanh.approx.f32 %0, %1;" : "=f"(y) : "f"(x)); return y;
}
__device__ __forceinline__ __nv_bfloat162 u2b(uint u) {
    return *reinterpret_cast<__nv_bfloat162*>(&u);
}
// ---- tf32 helpers ----
__device__ __forceinline__ uint f2tf32(float x) {
    uint u; asm("cvt.rna.tf32.f32 %0, %1;" : "=r"(u) : "f"(x)); return u;
}
__device__ __forceinline__ void mma_tf32(float& d0, float& d1, float& d2, float& d3,
                                         uint a0, uint a1, uint a2, uint a3,
                                         uint b0, uint b1) {
    asm("mma.sync.aligned.m16n8k8.row.col.f32.tf32.tf32.f32 "
        "{%0,%1,%2,%3}, {%4,%5,%6,%7}, {%8,%9}, {%0,%1,%2,%3};"
        : "+f"(d0), "+f"(d1), "+f"(d2), "+f"(d3)
        : "r"(a0), "r"(a1), "r"(a2), "r"(a3), "r"(b0), "r"(b1));
}

// ---------------- scratch (device globals; allocation-free) ----------------
__device__ float g_nl[NN*CG];
__device__ float g_nr[NN*CG];
__device__ float g_z[(size_t)EE*CZ];
__device__ float g_qkvo[(size_t)EE*512];        // q[0:128) k[128:256) v[256:384) sig(og)[384:512)
__device__ float g_bias[(size_t)NN*NH*KK*KK];   // [n][h][i][j]
__device__ float g_og[(size_t)EE*CZ];
__device__ float g_wcat[CZ*512];
__device__ float g_bcat[512];
__device__ uint  g_tab[TAB_N*CZ];               // [d][c] = bf16x2(db(d*h,c), db(d*h+h,c))

// ---------------- kernel: build db lookup table ----------------
__global__ void k_dbtab(const float* __restrict__ wdist, const float* __restrict__ b_dist)
{
    int d = blockIdx.x;     // 0..TAB_N-1
    int c = threadIdx.x;    // 0..127
    float d0 = d * TAB_H;
    float d1 = d0 + TAB_H;
    float v0 = b_dist[c], v1 = v0;
    #pragma unroll 4
    for (int r = 0; r < NRBF; r++) {
        float mu = (float)r * (20.0f/63.0f);
        float w  = __ldg(wdist + r*CZ + c);
        float x0 = (d0 - mu) * 3.2f;
        float x1 = (d1 - mu) * 3.2f;
        v0 += __expf(-x0*x0) * w;
        v1 += __expf(-x1*x1) * w;
    }
    __nv_bfloat162 p = __floats2bfloat162_rn(v0, v1);
    g_tab[d*CZ + c] = *reinterpret_cast<uint*>(&p);
}

// ---------------- kernel: concat projection weights ----------------
__global__ void k_concat(const float* __restrict__ wq, const float* __restrict__ bq,
                         const float* __restrict__ wkv, const float* __restrict__ bkv,
                         const float* __restrict__ wog, const float* __restrict__ bog)
{
    int c = blockIdx.x;
    int t = threadIdx.x;
    float v;
    if (t < 128)       v = wq[c*128 + t];
    else if (t < 384)  v = wkv[c*256 + (t-128)];
    else               v = wog[c*128 + (t-384)];
    g_wcat[c*512 + t] = v;
    if (c == 0) {
        float b;
        if (t < 128)      b = bq[t];
        else if (t < 384) b = bkv[t-128];
        else              b = bog[t-384];
        g_bcat[t] = b;
    }
}

// ---------------- kernel: node left/right projections ----------------
__global__ void k_nlr(const float* __restrict__ nf,
                      const float* __restrict__ wl, const float* __restrict__ bl,
                      const float* __restrict__ wr, const float* __restrict__ br)
{
    int n = blockIdx.x;
    int t = threadIdx.x;          // 32 threads
    int c0 = t & 15;
    const float* w = (t < 16) ? wl : wr;
    float acc = (t < 16) ? bl[c0] : br[c0];
    const float* row = nf + (size_t)n*CS;
    #pragma unroll 4
    for (int c = 0; c < CS; c++) acc += __ldg(row + c) * __ldg(w + c*CG + c0);
    if (t < 16) g_nl[n*CG + c0] = acc;
    else        g_nr[n*CG + c0] = acc;
}

// ---------------- kernel: LayerNorm over c_z ----------------
__global__ __launch_bounds__(128) void k_ln(const float* __restrict__ ef,
                                            const float* __restrict__ gam,
                                            const float* __restrict__ bet)
{
    int e = blockIdx.x;
    int t = threadIdx.x;
    float x = ef[(size_t)e*CZ + t];
    float s = x, s2 = x*x;
    #pragma unroll
    for (int o = 16; o > 0; o >>= 1) {
        s  += __shfl_xor_sync(0xffffffffu, s,  o);
        s2 += __shfl_xor_sync(0xffffffffu, s2, o);
    }
    __shared__ float ws[4], ws2[4];
    int w = t >> 5;
    if ((t & 31) == 0) { ws[w] = s; ws2[w] = s2; }
    __syncthreads();
    s  = ws[0]  + ws[1]  + ws[2]  + ws[3];
    s2 = ws2[0] + ws2[1] + ws2[2] + ws2[3];
    float mu  = s  * (1.f/128.f);
    float var = s2 * (1.f/128.f) - mu*mu;
    float inv = rsqrtf(var + 1e-5f);
    g_z[(size_t)e*CZ + t] = (x - mu) * inv * gam[t] + bet[t];
}

// ---------------- kernel: tf32 tensor-core GEMM ----------------
__global__ __launch_bounds__(256) void k_gemm_tc(const float* __restrict__ A,
                                                 const float* __restrict__ B,
                                                 float* __restrict__ C,
                                                 int ldb,
                                                 const float* __restrict__ bias,
                                                 int sigStart)
{
    __shared__ uint As[32*132];   // [k][m] tf32 bits
    __shared__ uint Bs[32*132];   // [k][n] tf32 bits
    int tid = threadIdx.x;
    int row0 = blockIdx.x * 128;
    int n0   = blockIdx.y * 128;
    int wid  = tid >> 5;
    int lane = tid & 31;
    int warp_m = wid >> 2;          // 0..1
    int warp_n = wid & 3;           // 0..3
    int gid = lane >> 2;            // 0..7
    int tig = lane & 3;             // 0..3
    int m0w = warp_m * 64;
    int n0w = warp_n * 32;

    float acc[4][4][4];
    #pragma unroll
    for (int mt = 0; mt < 4; mt++)
        #pragma unroll
        for (int nt = 0; nt < 4; nt++)
            #pragma unroll
            for (int q = 0; q < 4; q++) acc[mt][nt][q] = 0.f;

    for (int k0 = 0; k0 < 128; k0 += 32) {
        #pragma unroll
        for (int it = 0; it < 4; it++) {
            int idx = tid + it*256;
            int r = idx >> 3, kc = idx & 7;
            float4 v = *(const float4*)(A + (size_t)(row0 + r)*128 + k0 + kc*4);
            As[(kc*4+0)*132 + r] = f2tf32(v.x);
            As[(kc*4+1)*132 + r] = f2tf32(v.y);
            As[(kc*4+2)*132 + r] = f2tf32(v.z);
            As[(kc*4+3)*132 + r] = f2tf32(v.w);
        }
        #pragma unroll
        for (int it = 0; it < 4; it++) {
            int idx = tid + it*256;
            int r = idx >> 5, nc = idx & 31;
            float4 v = *(const float4*)(B + (size_t)(k0 + r)*ldb + n0 + nc*4);
            Bs[r*132 + nc*4 + 0] = f2tf32(v.x);
            Bs[r*132 + nc*4 + 1] = f2tf32(v.y);
            Bs[r*132 + nc*4 + 2] = f2tf32(v.z);
            Bs[r*132 + nc*4 + 3] = f2tf32(v.w);
        }
        __syncthreads();
        #pragma unroll
        for (int ks = 0; ks < 4; ks++) {
            int kb = ks * 8;
            const uint* a_lo = As + (kb + tig    )*132;
            const uint* a_hi = As + (kb + tig + 4)*132;
            uint af[4][4];
            #pragma unroll
            for (int mt = 0; mt < 4; mt++) {
                int ra = m0w + mt*16 + gid;
                af[mt][0] = a_lo[ra];
                af[mt][1] = a_lo[ra + 8];
                af[mt][2] = a_hi[ra];
                af[mt][3] = a_hi[ra + 8];
            }
            const uint* b_lo = Bs + (kb + tig    )*132;
            const uint* b_hi = Bs + (kb + tig + 4)*132;
            uint bf[4][2];
            #pragma unroll
            for (int nt = 0; nt < 4; nt++) {
                int cb = n0w + nt*8 + gid;
                bf[nt][0] = b_lo[cb];
                bf[nt][1] = b_hi[cb];
            }
            #pragma unroll
            for (int mt = 0; mt < 4; mt++)
                #pragma unroll
                for (int nt = 0; nt < 4; nt++)
                    mma_tf32(acc[mt][nt][0], acc[mt][nt][1], acc[mt][nt][2], acc[mt][nt][3],
                             af[mt][0], af[mt][1], af[mt][2], af[mt][3],
                             bf[nt][0], bf[nt][1]);
        }
        __syncthreads();
    }
    #pragma unroll
    for (int mt = 0; mt < 4; mt++) {
        int rowa = row0 + m0w + mt*16 + gid;
        #pragma unroll
        for (int nt = 0; nt < 4; nt++) {
            int col = n0 + n0w + nt*8 + 2*tig;
            float b0 = __ldg(bias + col), b1 = __ldg(bias + col + 1);
            float v0 = acc[mt][nt][0] + b0;
            float v1 = acc[mt][nt][1] + b1;
            float v2 = acc[mt][nt][2] + b0;
            float v3 = acc[mt][nt][3] + b1;
            if (col   >= sigStart) { v0 = __fdividef(1.f, 1.f + __expf(-v0));
                                     v2 = __fdividef(1.f, 1.f + __expf(-v2)); }
            if (col+1 >= sigStart) { v1 = __fdividef(1.f, 1.f + __expf(-v1));
                                     v3 = __fdividef(1.f, 1.f + __expf(-v3)); }
            float2 s0 = {v0, v1};
            float2 s1 = {v2, v3};
            *(float2*)(C + (size_t)rowa*ldb + col)     = s0;
            *(float2*)(C + (size_t)(rowa+8)*ldb + col) = s1;
        }
    }
}

// ---------------- kernel: triangle bias ----------------
// gate[i,j,c] = sum_k e1[i,k] * M[c,j,k],  M[c,j,k] = sum_l e2[j,l] W[k*16+l,c].
// db via precomputed table (lerp). R14 showed L1 at 57.5% but occ 24.9% and
// issue 33% -> latency-bound. Fix: __launch_bounds__(512, 2) caps regs at 64
// so TWO blocks fit the RF -> 32 warps/SM. Smem 43KB x 2 = 86KB < 228KB.
__global__ __launch_bounds__(512, 2) void k_tri(const int* __restrict__ ei,
                                                const float* __restrict__ trans,
                                                const float* __restrict__ W,       // [256,128]
                                                const float* __restrict__ b_bgate,
                                                const float* __restrict__ wtob)    // [128,4]
{
    __shared__ float          s_e2t[16*32];      // [l][j]                  2048B
    __shared__ float          s_t[32*4];         //                          512B
    __shared__ ull            s_wt2[128*2];      // [c][h-pair]             2048B
    __shared__ __nv_bfloat16  s_M[16*32*16];     // [c][j][k] bf16         16384B
    __shared__ uint           s_tab[TAB_N*20];   // [d][cl], stride 20     21760B
    __shared__ float          s_bg[128];         //                          512B
    __shared__ int            s_src[32];         //                          128B

    int n = blockIdx.x;
    int tid = threadIdx.x;

    if (tid < 32) s_src[tid] = ei[n*KK + tid];
    __syncthreads();
    {
        int i = tid >> 4, k = tid & 15;
        s_e2t[k*32 + i] = g_nr[s_src[i]*CG + k];
    }
    if (tid < 256) {
        int c = tid >> 1, p = tid & 1;
        s_wt2[c*2 + p] = pk2(wtob[c*4 + 2*p], wtob[c*4 + 2*p + 1]);
    }
    if (tid < 96) { int i = tid/3, c = tid - i*3; s_t[i*4+c] = trans[s_src[i]*3 + c]; }
    if (tid < 128) s_bg[tid] = b_bgate[tid];
    __syncthreads();

    // ---- phase B pair assignment: thread = (j, {ib, ib+1}) ----
    int j  = tid >> 4;              // 0..31
    int ib = (tid & 15) * 2;

    int   idxp[2];
    float frac[2];
    __nv_bfloat162 e1h[2][8];       // e1[i,:] pair-packed bf16
    #pragma unroll
    for (int ii = 0; ii < 2; ii++) {
        int i = ib + ii;
        float dx = s_t[i*4+0] - s_t[j*4+0] + 1e-8f;
        float dy = s_t[i*4+1] - s_t[j*4+1] + 1e-8f;
        float dz = s_t[i*4+2] - s_t[j*4+2] + 1e-8f;
        float dd = sqrtf(dx*dx + dy*dy + dz*dz);
        dd = fminf(dd, TAB_DMAX);
        float u = dd * TAB_INVH;
        int idx = (int)u;
        idxp[ii] = idx;
        frac[ii] = u - (float)idx;
        const float4* ep = (const float4*)(g_nl + s_src[i]*CG);
        #pragma unroll
        for (int q = 0; q < 4; q++) {
            float4 e4 = __ldg(ep + q);
            e1h[ii][2*q  ] = __floats2bfloat162_rn(e4.x, e4.y);
            e1h[ii][2*q+1] = __floats2bfloat162_rn(e4.z, e4.w);
        }
    }

    // ---- phase A assignment: jA = lane, kA WARP-UNIFORM -> W broadcasts ----
    int jA = tid & 31;
    int kA = tid >> 5;

    ull bacc[2][2] = {{0ull, 0ull}, {0ull, 0ull}};   // [ii][h-pair], f32x2

    for (int ch = 0; ch < 8; ch++) {
        int cb = ch * 16;
        // stage db-table slice: s_tab[d*20 + cl] = g_tab[d*128 + cb + cl]
        for (int p = tid; p < TAB_N*16; p += 512) {
            int d = p >> 4, cl = p & 15;
            s_tab[d*20 + cl] = __ldg(g_tab + d*CZ + cb + cl);
        }
        // phase A: M[c][j][k] = sum_l e2[j,l] * W[(k*16+l)*128 + cb+c]
        // two 4-channel halves to keep live accumulators at 8 regs
        #pragma unroll
        for (int half = 0; half < 2; half++) {
            ull a2[4] = {0ull, 0ull, 0ull, 0ull};
            #pragma unroll
            for (int l = 0; l < 16; l++) {
                float e2v = s_e2t[l*32 + jA];
                ull e2p = pk2(e2v, e2v);
                const ulonglong2* Wp = (const ulonglong2*)(W + (size_t)(kA*16 + l)*128 + cb + half*8);
                ulonglong2 w01 = __ldg(Wp+0), w23 = __ldg(Wp+1);
                a2[0] = ffma2(e2p, w01.x, a2[0]); a2[1] = ffma2(e2p, w01.y, a2[1]);
                a2[2] = ffma2(e2p, w23.x, a2[2]); a2[3] = ffma2(e2p, w23.y, a2[3]);
            }
            #pragma unroll
            for (int c2 = 0; c2 < 4; c2++) {
                float lo, hi;
                upk2(a2[c2], lo, hi);
                int cloc = half*8 + 2*c2;
                s_M[((cloc  )*32 + jA)*16 + kA] = __float2bfloat16_rn(lo);
                s_M[((cloc+1)*32 + jA)*16 + kA] = __float2bfloat16_rn(hi);
            }
        }
        __syncthreads();
        // phase B: 4 channel-quads; one LDS.128 per (ii, quad) covers 4 channels
        #pragma unroll 1
        for (int q4 = 0; q4 < 4; q4++) {
            uint4 tq0 = *(const uint4*)(s_tab + idxp[0]*20 + q4*4);
            uint4 tq1 = *(const uint4*)(s_tab + idxp[1]*20 + q4*4);
            uint ta0[4] = {tq0.x, tq0.y, tq0.z, tq0.w};
            uint ta1[4] = {tq1.x, tq1.y, tq1.z, tq1.w};
            #pragma unroll
            for (int c2 = 0; c2 < 4; c2++) {
                int cc = q4*4 + c2;
                int c = cb + cc;
                const __nv_bfloat16* mrow = s_M + (cc*32 + j)*16;   // broadcast (j warp-uniform)
                uint4 ma = *(const uint4*)(mrow);
                uint4 mb = *(const uint4*)(mrow + 8);
                float bg = s_bg[c];
                float t01[2];
                #pragma unroll
                for (int ii = 0; ii < 2; ii++) {
                    __nv_bfloat162 ga = __floats2bfloat162_rn(0.f, 0.f);
                    ga = __hfma2(e1h[ii][0], u2b(ma.x), ga);
                    ga = __hfma2(e1h[ii][1], u2b(ma.y), ga);
                    ga = __hfma2(e1h[ii][2], u2b(ma.z), ga);
                    ga = __hfma2(e1h[ii][3], u2b(ma.w), ga);
                    ga = __hfma2(e1h[ii][4], u2b(mb.x), ga);
                    ga = __hfma2(e1h[ii][5], u2b(mb.y), ga);
                    ga = __hfma2(e1h[ii][6], u2b(mb.z), ga);
                    ga = __hfma2(e1h[ii][7], u2b(mb.w), ga);
                    float g = __low2float(ga) + __high2float(ga) + bg;
                    float sg = 0.5f + 0.5f*tanh_fast(0.5f*g);
                    uint tv = (ii == 0) ? ta0[c2] : ta1[c2];
                    float2 t2 = __bfloat1622float2(u2b(tv));
                    float db = t2.x + frac[ii]*(t2.y - t2.x);
                    t01[ii] = sg * db;
                }
                const ull* wt = s_wt2 + c*2;
                ull wt0 = wt[0], wt1 = wt[1];
                ull tp0 = pk2(t01[0], t01[0]);
                ull tp1 = pk2(t01[1], t01[1]);
                bacc[0][0] = ffma2(tp0, wt0, bacc[0][0]);
                bacc[0][1] = ffma2(tp0, wt1, bacc[0][1]);
                bacc[1][0] = ffma2(tp1, wt0, bacc[1][0]);
                bacc[1][1] = ffma2(tp1, wt1, bacc[1][1]);
            }
        }
        __syncthreads();
    }
    #pragma unroll
    for (int ii = 0; ii < 2; ii++) {
        int i = ib + ii;
        float b0, b1, b2, b3;
        upk2(bacc[ii][0], b0, b1);
        upk2(bacc[ii][1], b2, b3);
        g_bias[(((size_t)n*NH + 0)*KK + i)*KK + j] = b0;
        g_bias[(((size_t)n*NH + 1)*KK + i)*KK + j] = b1;
        g_bias[(((size_t)n*NH + 2)*KK + i)*KK + j] = b2;
        g_bias[(((size_t)n*NH + 3)*KK + i)*KK + j] = b3;
    }
}

// ---------------- kernel: attention over K neighbors, per node ----------------
__global__ __launch_bounds__(128) void k_attn()
{
    int n = blockIdx.x;
    int tid = threadIdx.x;
    int h = tid >> 5, i = tid & 31;
    __shared__ float sk[KK*CZ];
    __shared__ float sv[KK*CZ];
    for (int p = tid; p < KK*CZ; p += 128) {
        int jj = p >> 7, c = p & 127;
        size_t base = (size_t)(n*KK + jj) * 512;
        sk[p] = g_qkvo[base + 128 + c];
        sv[p] = g_qkvo[base + 256 + c];
    }
    float qr[32];
    const float scale = 0.17677669529663687f;   // 1/sqrt(32)
    size_t erow = (size_t)(n*KK + i) * 512;
    #pragma unroll
    for (int d = 0; d < 32; d++) qr[d] = g_qkvo[erow + h*32 + d] * scale;
    __syncthreads();

    float s[32];
    float mx = -1e30f;
    const float* bp = g_bias + (((size_t)n*NH + h)*KK + i)*KK;
    #pragma unroll
    for (int jj = 0; jj < 32; jj++) {
        float acc = bp[jj];
        const float* kp = sk + jj*128 + h*32;
        #pragma unroll
        for (int d = 0; d < 32; d++) acc += qr[d] * kp[d];
        s[jj] = acc;
        mx = fmaxf(mx, acc);
    }
    float sum = 0.f;
    #pragma unroll
    for (int jj = 0; jj < 32; jj++) { s[jj] = __expf(s[jj] - mx); sum += s[jj]; }
    float inv = __fdividef(1.f, sum);
    float* op = g_og + (size_t)(n*KK + i)*CZ + h*32;
    const float* ogp = g_qkvo + erow + 384 + h*32;
    #pragma unroll
    for (int d = 0; d < 32; d++) {
        float acc = 0.f;
        const float* vp = sv + h*32 + d;
        #pragma unroll
        for (int jj = 0; jj < 32; jj++) acc += s[jj] * vp[jj*128];
        op[d] = acc * inv * ogp[d];
    }
}

// ---------------- launch ----------------
extern "C" void kernel_launch(void* const* d_in, const int* in_sizes, int n_in,
                              void* d_out, int out_size)
{
    const float* nf       = (const float*)d_in[0];
    const float* trans    = (const float*)d_in[1];
    const float* ef       = (const float*)d_in[2];
    const int*   ei       = (const int*)d_in[3];
    const float* w_left   = (const float*)d_in[4];
    const float* b_left   = (const float*)d_in[5];
    const float* w_right  = (const float*)d_in[6];
    const float* b_right  = (const float*)d_in[7];
    const float* w_bgate  = (const float*)d_in[8];
    const float* b_bgate  = (const float*)d_in[9];
    const float* w_dist   = (const float*)d_in[10];
    const float* b_dist   = (const float*)d_in[11];
    const float* w_tobias = (const float*)d_in[12];
    const float* ln_g     = (const float*)d_in[13];
    const float* ln_b     = (const float*)d_in[14];
    const float* w_q      = (const float*)d_in[15];
    const float* b_q      = (const float*)d_in[16];
    const float* w_kv     = (const float*)d_in[17];
    const float* b_kv     = (const float*)d_in[18];
    const float* w_out    = (const float*)d_in[19];
    const float* b_out    = (const float*)d_in[20];
    const float* w_ogate  = (const float*)d_in[21];
    const float* b_ogate  = (const float*)d_in[22];
    float* out = (float*)d_out;

    float *p_z, *p_qkvo, *p_og, *p_wcat, *p_bcat;
    cudaGetSymbolAddress((void**)&p_z,    g_z);
    cudaGetSymbolAddress((void**)&p_qkvo, g_qkvo);
    cudaGetSymbolAddress((void**)&p_og,   g_og);
    cudaGetSymbolAddress((void**)&p_wcat, g_wcat);
    cudaGetSymbolAddress((void**)&p_bcat, g_bcat);

    // k_tri is launch #4 (ncu -s 5 -c 1 capture slot)
    k_concat<<<128, 512>>>(w_q, b_q, w_kv, b_kv, w_ogate, b_ogate);
    k_dbtab<<<TAB_N, 128>>>(w_dist, b_dist);
    k_nlr<<<NN, 32>>>(nf, w_left, b_left, w_right, b_right);
    k_tri<<<NN, 512>>>(ei, trans, w_bgate, b_bgate, w_tobias);
    k_ln<<<EE, 128>>>(ef, ln_g, ln_b);
    {
        dim3 g(EE/128, 512/128);
        k_gemm_tc<<<g, 256>>>(p_z, p_wcat, p_qkvo, 512, p_bcat, 384);
    }
    k_attn<<<NN, 128>>>();
    {
        dim3 g(EE/128, 1);
        k_gemm_tc<<<g, 256>>>(p_og, w_out, out, 128, b_out, 1 << 30);
    }
}

// round 16
// speedup vs baseline: 2.3978x; 1.0308x over previous
#include <cuda_runtime.h>
#include <cuda_bf16.h>
#include <math.h>

#define NN   768
#define KK   32
#define CS   384
#define CZ   128
#define CG   16
#define NH   4
#define EE   (NN*KK)
#define NRBF 64

// db lookup table: d grid step 0.16, 136 points, covers d in [0, 21.6]
#define TAB_H    0.16f
#define TAB_INVH 6.25f
#define TAB_N    136
#define TAB_DMAX 21.4f

typedef unsigned long long ull;
typedef unsigned int uint;

// ---- f32x2 packed helpers (sm_100+) ----
__device__ __forceinline__ ull pk2(float lo, float hi) {
    ull r; asm("mov.b64 %0, {%1,%2};" : "=l"(r) : "f"(lo), "f"(hi)); return r;
}
__device__ __forceinline__ void upk2(ull v, float& lo, float& hi) {
    asm("mov.b64 {%0,%1}, %2;" : "=f"(lo), "=f"(hi) : "l"(v));
}
__device__ __forceinline__ ull ffma2(ull a, ull b, ull c) {
    ull d; asm("fma.rn.f32x2 %0, %1, %2, %3;" : "=l"(d) : "l"(a), "l"(b), "l"(c)); return d;
}
__device__ __forceinline__ float tanh_fast(float x) {
    float y; asm("tanh.approx.f32 %0, %1;" : "=f"(y) : "f"(x)); return y;
}
__device__ __forceinline__ __nv_bfloat162 u2b(uint u) {
    return *reinterpret_cast<__nv_bfloat162*>(&u);
}
// ---- tf32 helpers ----
__device__ __forceinline__ uint f2tf32(float x) {
    uint u; asm("cvt.rna.tf32.f32 %0, %1;" : "=r"(u) : "f"(x)); return u;
}
__device__ __forceinline__ void mma_tf32(float& d0, float& d1, float& d2, float& d3,
                                         uint a0, uint a1, uint a2, uint a3,
                                         uint b0, uint b1) {
    asm("mma.sync.aligned.m16n8k8.row.col.f32.tf32.tf32.f32 "
        "{%0,%1,%2,%3}, {%4,%5,%6,%7}, {%8,%9}, {%0,%1,%2,%3};"
        : "+f"(d0), "+f"(d1), "+f"(d2), "+f"(d3)
        : "r"(a0), "r"(a1), "r"(a2), "r"(a3), "r"(b0), "r"(b1));
}

// ---------------- scratch (device globals; allocation-free) ----------------
__device__ float g_nl[NN*CG];
__device__ float g_nr[NN*CG];
__device__ float g_z[(size_t)EE*CZ];
__device__ float g_qkvo[(size_t)EE*512];        // q[0:128) k[128:256) v[256:384) sig(og)[384:512)
__device__ float g_bias[(size_t)NN*NH*KK*KK];   // [n][h][i][j]
__device__ float g_og[(size_t)EE*CZ];
__device__ float g_wcat[CZ*512];
__device__ float g_bcat[512];
__device__ uint  g_tab[TAB_N*CZ];               // [d][c] = bf16x2(db(d*h,c), db(d*h+h,c))

// ---------------- kernel: build db lookup table ----------------
__global__ void k_dbtab(const float* __restrict__ wdist, const float* __restrict__ b_dist)
{
    int d = blockIdx.x;     // 0..TAB_N-1
    int c = threadIdx.x;    // 0..127
    float d0 = d * TAB_H;
    float d1 = d0 + TAB_H;
    float v0 = b_dist[c], v1 = v0;
    #pragma unroll 4
    for (int r = 0; r < NRBF; r++) {
        float mu = (float)r * (20.0f/63.0f);
        float w  = __ldg(wdist + r*CZ + c);
        float x0 = (d0 - mu) * 3.2f;
        float x1 = (d1 - mu) * 3.2f;
        v0 += __expf(-x0*x0) * w;
        v1 += __expf(-x1*x1) * w;
    }
    __nv_bfloat162 p = __floats2bfloat162_rn(v0, v1);
    g_tab[d*CZ + c] = *reinterpret_cast<uint*>(&p);
}

// ---------------- kernel: concat projection weights ----------------
__global__ void k_concat(const float* __restrict__ wq, const float* __restrict__ bq,
                         const float* __restrict__ wkv, const float* __restrict__ bkv,
                         const float* __restrict__ wog, const float* __restrict__ bog)
{
    int c = blockIdx.x;
    int t = threadIdx.x;
    float v;
    if (t < 128)       v = wq[c*128 + t];
    else if (t < 384)  v = wkv[c*256 + (t-128)];
    else               v = wog[c*128 + (t-384)];
    g_wcat[c*512 + t] = v;
    if (c == 0) {
        float b;
        if (t < 128)      b = bq[t];
        else if (t < 384) b = bkv[t-128];
        else              b = bog[t-384];
        g_bcat[t] = b;
    }
}

// ---------------- kernel: node left/right projections ----------------
__global__ void k_nlr(const float* __restrict__ nf,
                      const float* __restrict__ wl, const float* __restrict__ bl,
                      const float* __restrict__ wr, const float* __restrict__ br)
{
    int n = blockIdx.x;
    int t = threadIdx.x;          // 32 threads
    int c0 = t & 15;
    const float* w = (t < 16) ? wl : wr;
    float acc = (t < 16) ? bl[c0] : br[c0];
    const float* row = nf + (size_t)n*CS;
    #pragma unroll 4
    for (int c = 0; c < CS; c++) acc += __ldg(row + c) * __ldg(w + c*CG + c0);
    if (t < 16) g_nl[n*CG + c0] = acc;
    else        g_nr[n*CG + c0] = acc;
}

// ---------------- kernel: LayerNorm over c_z ----------------
__global__ __launch_bounds__(128) void k_ln(const float* __restrict__ ef,
                                            const float* __restrict__ gam,
                                            const float* __restrict__ bet)
{
    int e = blockIdx.x;
    int t = threadIdx.x;
    float x = ef[(size_t)e*CZ + t];
    float s = x, s2 = x*x;
    #pragma unroll
    for (int o = 16; o > 0; o >>= 1) {
        s  += __shfl_xor_sync(0xffffffffu, s,  o);
        s2 += __shfl_xor_sync(0xffffffffu, s2, o);
    }
    __shared__ float ws[4], ws2[4];
    int w = t >> 5;
    if ((t & 31) == 0) { ws[w] = s; ws2[w] = s2; }
    __syncthreads();
    s  = ws[0]  + ws[1]  + ws[2]  + ws[3];
    s2 = ws2[0] + ws2[1] + ws2[2] + ws2[3];
    float mu  = s  * (1.f/128.f);
    float var = s2 * (1.f/128.f) - mu*mu;
    float inv = rsqrtf(var + 1e-5f);
    g_z[(size_t)e*CZ + t] = (x - mu) * inv * gam[t] + bet[t];
}

// ---------------- kernel: tf32 tensor-core GEMM ----------------
__global__ __launch_bounds__(256) void k_gemm_tc(const float* __restrict__ A,
                                                 const float* __restrict__ B,
                                                 float* __restrict__ C,
                                                 int ldb,
                                                 const float* __restrict__ bias,
                                                 int sigStart)
{
    __shared__ uint As[32*132];   // [k][m] tf32 bits
    __shared__ uint Bs[32*132];   // [k][n] tf32 bits
    int tid = threadIdx.x;
    int row0 = blockIdx.x * 128;
    int n0   = blockIdx.y * 128;
    int wid  = tid >> 5;
    int lane = tid & 31;
    int warp_m = wid >> 2;          // 0..1
    int warp_n = wid & 3;           // 0..3
    int gid = lane >> 2;            // 0..7
    int tig = lane & 3;             // 0..3
    int m0w = warp_m * 64;
    int n0w = warp_n * 32;

    float acc[4][4][4];
    #pragma unroll
    for (int mt = 0; mt < 4; mt++)
        #pragma unroll
        for (int nt = 0; nt < 4; nt++)
            #pragma unroll
            for (int q = 0; q < 4; q++) acc[mt][nt][q] = 0.f;

    for (int k0 = 0; k0 < 128; k0 += 32) {
        #pragma unroll
        for (int it = 0; it < 4; it++) {
            int idx = tid + it*256;
            int r = idx >> 3, kc = idx & 7;
            float4 v = *(const float4*)(A + (size_t)(row0 + r)*128 + k0 + kc*4);
            As[(kc*4+0)*132 + r] = f2tf32(v.x);
            As[(kc*4+1)*132 + r] = f2tf32(v.y);
            As[(kc*4+2)*132 + r] = f2tf32(v.z);
            As[(kc*4+3)*132 + r] = f2tf32(v.w);
        }
        #pragma unroll
        for (int it = 0; it < 4; it++) {
            int idx = tid + it*256;
            int r = idx >> 5, nc = idx & 31;
            float4 v = *(const float4*)(B + (size_t)(k0 + r)*ldb + n0 + nc*4);
            Bs[r*132 + nc*4 + 0] = f2tf32(v.x);
            Bs[r*132 + nc*4 + 1] = f2tf32(v.y);
            Bs[r*132 + nc*4 + 2] = f2tf32(v.z);
            Bs[r*132 + nc*4 + 3] = f2tf32(v.w);
        }
        __syncthreads();
        #pragma unroll
        for (int ks = 0; ks < 4; ks++) {
            int kb = ks * 8;
            const uint* a_lo = As + (kb + tig    )*132;
            const uint* a_hi = As + (kb + tig + 4)*132;
            uint af[4][4];
            #pragma unroll
            for (int mt = 0; mt < 4; mt++) {
                int ra = m0w + mt*16 + gid;
                af[mt][0] = a_lo[ra];
                af[mt][1] = a_lo[ra + 8];
                af[mt][2] = a_hi[ra];
                af[mt][3] = a_hi[ra + 8];
            }
            const uint* b_lo = Bs + (kb + tig    )*132;
            const uint* b_hi = Bs + (kb + tig + 4)*132;
            uint bf[4][2];
            #pragma unroll
            for (int nt = 0; nt < 4; nt++) {
                int cb = n0w + nt*8 + gid;
                bf[nt][0] = b_lo[cb];
                bf[nt][1] = b_hi[cb];
            }
            #pragma unroll
            for (int mt = 0; mt < 4; mt++)
                #pragma unroll
                for (int nt = 0; nt < 4; nt++)
                    mma_tf32(acc[mt][nt][0], acc[mt][nt][1], acc[mt][nt][2], acc[mt][nt][3],
                             af[mt][0], af[mt][1], af[mt][2], af[mt][3],
                             bf[nt][0], bf[nt][1]);
        }
        __syncthreads();
    }
    #pragma unroll
    for (int mt = 0; mt < 4; mt++) {
        int rowa = row0 + m0w + mt*16 + gid;
        #pragma unroll
        for (int nt = 0; nt < 4; nt++) {
            int col = n0 + n0w + nt*8 + 2*tig;
            float b0 = __ldg(bias + col), b1 = __ldg(bias + col + 1);
            float v0 = acc[mt][nt][0] + b0;
            float v1 = acc[mt][nt][1] + b1;
            float v2 = acc[mt][nt][2] + b0;
            float v3 = acc[mt][nt][3] + b1;
            if (col   >= sigStart) { v0 = __fdividef(1.f, 1.f + __expf(-v0));
                                     v2 = __fdividef(1.f, 1.f + __expf(-v2)); }
            if (col+1 >= sigStart) { v1 = __fdividef(1.f, 1.f + __expf(-v1));
                                     v3 = __fdividef(1.f, 1.f + __expf(-v3)); }
            float2 s0 = {v0, v1};
            float2 s1 = {v2, v3};
            *(float2*)(C + (size_t)rowa*ldb + col)     = s0;
            *(float2*)(C + (size_t)(rowa+8)*ldb + col) = s1;
        }
    }
}

// ---------------- kernel: triangle bias ----------------
// gate[i,j,c] = sum_k e1[i,k] * M[c,j,k],  M[c,j,k] = sum_l e2[j,l] W[k*16+l,c].
// db via precomputed table (lerp). This round: s_M row stride 24 bf16 (48B,
// 16B-aligned) cuts the phase-A STS.U16 conflict from 8-way to 4-way; table
// at h=0.16 frees the smem; gate accumulation split into two independent
// HFMA2 chains to halve the dependency depth.
__global__ __launch_bounds__(512, 2) void k_tri(const int* __restrict__ ei,
                                                const float* __restrict__ trans,
                                                const float* __restrict__ W,       // [256,128]
                                                const float* __restrict__ b_bgate,
                                                const float* __restrict__ wtob)    // [128,4]
{
    __shared__ float          s_e2t[16*32];      // [l][j]                  2048B
    __shared__ float          s_t[32*4];         //                          512B
    __shared__ ull            s_wt2[128*2];      // [c][h-pair]             2048B
    __shared__ __nv_bfloat16  s_M[16*32*24];     // [c][j][k] bf16, str 24 24576B
    __shared__ uint           s_tab[TAB_N*20];   // [d][cl], stride 20     10880B
    __shared__ float          s_bg[128];         //                          512B
    __shared__ int            s_src[32];         //                          128B

    int n = blockIdx.x;
    int tid = threadIdx.x;

    if (tid < 32) s_src[tid] = ei[n*KK + tid];
    __syncthreads();
    {
        int i = tid >> 4, k = tid & 15;
        s_e2t[k*32 + i] = g_nr[s_src[i]*CG + k];
    }
    if (tid < 256) {
        int c = tid >> 1, p = tid & 1;
        s_wt2[c*2 + p] = pk2(wtob[c*4 + 2*p], wtob[c*4 + 2*p + 1]);
    }
    if (tid < 96) { int i = tid/3, c = tid - i*3; s_t[i*4+c] = trans[s_src[i]*3 + c]; }
    if (tid < 128) s_bg[tid] = b_bgate[tid];
    __syncthreads();

    // ---- phase B pair assignment: thread = (j, {ib, ib+1}) ----
    int j  = tid >> 4;              // 0..31
    int ib = (tid & 15) * 2;

    int   idxp[2];
    float frac[2];
    __nv_bfloat162 e1h[2][8];       // e1[i,:] pair-packed bf16
    #pragma unroll
    for (int ii = 0; ii < 2; ii++) {
        int i = ib + ii;
        float dx = s_t[i*4+0] - s_t[j*4+0] + 1e-8f;
        float dy = s_t[i*4+1] - s_t[j*4+1] + 1e-8f;
        float dz = s_t[i*4+2] - s_t[j*4+2] + 1e-8f;
        float dd = sqrtf(dx*dx + dy*dy + dz*dz);
        dd = fminf(dd, TAB_DMAX);
        float u = dd * TAB_INVH;
        int idx = (int)u;
        idxp[ii] = idx;
        frac[ii] = u - (float)idx;
        const float4* ep = (const float4*)(g_nl + s_src[i]*CG);
        #pragma unroll
        for (int q = 0; q < 4; q++) {
            float4 e4 = __ldg(ep + q);
            e1h[ii][2*q  ] = __floats2bfloat162_rn(e4.x, e4.y);
            e1h[ii][2*q+1] = __floats2bfloat162_rn(e4.z, e4.w);
        }
    }

    // ---- phase A assignment: jA = lane, kA WARP-UNIFORM -> W broadcasts ----
    int jA = tid & 31;
    int kA = tid >> 5;

    ull bacc[2][2] = {{0ull, 0ull}, {0ull, 0ull}};   // [ii][h-pair], f32x2

    for (int ch = 0; ch < 8; ch++) {
        int cb = ch * 16;
        // stage db-table slice: s_tab[d*20 + cl] = g_tab[d*128 + cb + cl]
        for (int p = tid; p < TAB_N*16; p += 512) {
            int d = p >> 4, cl = p & 15;
            s_tab[d*20 + cl] = __ldg(g_tab + d*CZ + cb + cl);
        }
        // phase A: M[c][j][k] = sum_l e2[j,l] * W[(k*16+l)*128 + cb+c]
        // two 4-channel halves to keep live accumulators at 8 regs
        #pragma unroll
        for (int half = 0; half < 2; half++) {
            ull a2[4] = {0ull, 0ull, 0ull, 0ull};
            #pragma unroll
            for (int l = 0; l < 16; l++) {
                float e2v = s_e2t[l*32 + jA];
                ull e2p = pk2(e2v, e2v);
                const ulonglong2* Wp = (const ulonglong2*)(W + (size_t)(kA*16 + l)*128 + cb + half*8);
                ulonglong2 w01 = __ldg(Wp+0), w23 = __ldg(Wp+1);
                a2[0] = ffma2(e2p, w01.x, a2[0]); a2[1] = ffma2(e2p, w01.y, a2[1]);
                a2[2] = ffma2(e2p, w23.x, a2[2]); a2[3] = ffma2(e2p, w23.y, a2[3]);
            }
            #pragma unroll
            for (int c2 = 0; c2 < 4; c2++) {
                float lo, hi;
                upk2(a2[c2], lo, hi);
                int cloc = half*8 + 2*c2;
                s_M[((cloc  )*32 + jA)*24 + kA] = __float2bfloat16_rn(lo);
                s_M[((cloc+1)*32 + jA)*24 + kA] = __float2bfloat16_rn(hi);
            }
        }
        __syncthreads();
        // phase B: 4 channel-quads; one LDS.128 per (ii, quad) covers 4 channels
        #pragma unroll 1
        for (int q4 = 0; q4 < 4; q4++) {
            uint4 tq0 = *(const uint4*)(s_tab + idxp[0]*20 + q4*4);
            uint4 tq1 = *(const uint4*)(s_tab + idxp[1]*20 + q4*4);
            uint ta0[4] = {tq0.x, tq0.y, tq0.z, tq0.w};
            uint ta1[4] = {tq1.x, tq1.y, tq1.z, tq1.w};
            #pragma unroll
            for (int c2 = 0; c2 < 4; c2++) {
                int cc = q4*4 + c2;
                int c = cb + cc;
                const __nv_bfloat16* mrow = s_M + (cc*32 + j)*24;   // broadcast (j warp-uniform)
                uint4 ma = *(const uint4*)(mrow);
                uint4 mb = *(const uint4*)(mrow + 8);
                float bg = s_bg[c];
                float t01[2];
                #pragma unroll
                for (int ii = 0; ii < 2; ii++) {
                    // two independent 4-deep chains (was one 8-deep chain)
                    __nv_bfloat162 ga0 = __floats2bfloat162_rn(0.f, 0.f);
                    __nv_bfloat162 ga1 = __floats2bfloat162_rn(0.f, 0.f);
                    ga0 = __hfma2(e1h[ii][0], u2b(ma.x), ga0);
                    ga1 = __hfma2(e1h[ii][4], u2b(mb.x), ga1);
                    ga0 = __hfma2(e1h[ii][1], u2b(ma.y), ga0);
                    ga1 = __hfma2(e1h[ii][5], u2b(mb.y), ga1);
                    ga0 = __hfma2(e1h[ii][2], u2b(ma.z), ga0);
                    ga1 = __hfma2(e1h[ii][6], u2b(mb.z), ga1);
                    ga0 = __hfma2(e1h[ii][3], u2b(ma.w), ga0);
                    ga1 = __hfma2(e1h[ii][7], u2b(mb.w), ga1);
                    float g = __low2float(ga0) + __high2float(ga0)
                            + __low2float(ga1) + __high2float(ga1) + bg;
                    float sg = 0.5f + 0.5f*tanh_fast(0.5f*g);
                    uint tv = (ii == 0) ? ta0[c2] : ta1[c2];
                    float2 t2 = __bfloat1622float2(u2b(tv));
                    float db = t2.x + frac[ii]*(t2.y - t2.x);
                    t01[ii] = sg * db;
                }
                const ull* wt = s_wt2 + c*2;
                ull wt0 = wt[0], wt1 = wt[1];
                ull tp0 = pk2(t01[0], t01[0]);
                ull tp1 = pk2(t01[1], t01[1]);
                bacc[0][0] = ffma2(tp0, wt0, bacc[0][0]);
                bacc[0][1] = ffma2(tp0, wt1, bacc[0][1]);
                bacc[1][0] = ffma2(tp1, wt0, bacc[1][0]);
                bacc[1][1] = ffma2(tp1, wt1, bacc[1][1]);
            }
        }
        __syncthreads();
    }
    #pragma unroll
    for (int ii = 0; ii < 2; ii++) {
        int i = ib + ii;
        float b0, b1, b2, b3;
        upk2(bacc[ii][0], b0, b1);
        upk2(bacc[ii][1], b2, b3);
        g_bias[(((size_t)n*NH + 0)*KK + i)*KK + j] = b0;
        g_bias[(((size_t)n*NH + 1)*KK + i)*KK + j] = b1;
        g_bias[(((size_t)n*NH + 2)*KK + i)*KK + j] = b2;
        g_bias[(((size_t)n*NH + 3)*KK + i)*KK + j] = b3;
    }
}

// ---------------- kernel: attention over K neighbors, per node ----------------
__global__ __launch_bounds__(128) void k_attn()
{
    int n = blockIdx.x;
    int tid = threadIdx.x;
    int h = tid >> 5, i = tid & 31;
    __shared__ float sk[KK*CZ];
    __shared__ float sv[KK*CZ];
    for (int p = tid; p < KK*CZ; p += 128) {
        int jj = p >> 7, c = p & 127;
        size_t base = (size_t)(n*KK + jj) * 512;
        sk[p] = g_qkvo[base + 128 + c];
        sv[p] = g_qkvo[base + 256 + c];
    }
    float qr[32];
    const float scale = 0.17677669529663687f;   // 1/sqrt(32)
    size_t erow = (size_t)(n*KK + i) * 512;
    #pragma unroll
    for (int d = 0; d < 32; d++) qr[d] = g_qkvo[erow + h*32 + d] * scale;
    __syncthreads();

    float s[32];
    float mx = -1e30f;
    const float* bp = g_bias + (((size_t)n*NH + h)*KK + i)*KK;
    #pragma unroll
    for (int jj = 0; jj < 32; jj++) {
        float acc = bp[jj];
        const float* kp = sk + jj*128 + h*32;
        #pragma unroll
        for (int d = 0; d < 32; d++) acc += qr[d] * kp[d];
        s[jj] = acc;
        mx = fmaxf(mx, acc);
    }
    float sum = 0.f;
    #pragma unroll
    for (int jj = 0; jj < 32; jj++) { s[jj] = __expf(s[jj] - mx); sum += s[jj]; }
    float inv = __fdividef(1.f, sum);
    float* op = g_og + (size_t)(n*KK + i)*CZ + h*32;
    const float* ogp = g_qkvo + erow + 384 + h*32;
    #pragma unroll
    for (int d = 0; d < 32; d++) {
        float acc = 0.f;
        const float* vp = sv + h*32 + d;
        #pragma unroll
        for (int jj = 0; jj < 32; jj++) acc += s[jj] * vp[jj*128];
        op[d] = acc * inv * ogp[d];
    }
}

// ---------------- launch ----------------
extern "C" void kernel_launch(void* const* d_in, const int* in_sizes, int n_in,
                              void* d_out, int out_size)
{
    const float* nf       = (const float*)d_in[0];
    const float* trans    = (const float*)d_in[1];
    const float* ef       = (const float*)d_in[2];
    const int*   ei       = (const int*)d_in[3];
    const float* w_left   = (const float*)d_in[4];
    const float* b_left   = (const float*)d_in[5];
    const float* w_right  = (const float*)d_in[6];
    const float* b_right  = (const float*)d_in[7];
    const float* w_bgate  = (const float*)d_in[8];
    const float* b_bgate  = (const float*)d_in[9];
    const float* w_dist   = (const float*)d_in[10];
    const float* b_dist   = (const float*)d_in[11];
    const float* w_tobias = (const float*)d_in[12];
    const float* ln_g     = (const float*)d_in[13];
    const float* ln_b     = (const float*)d_in[14];
    const float* w_q      = (const float*)d_in[15];
    const float* b_q      = (const float*)d_in[16];
    const float* w_kv     = (const float*)d_in[17];
    const float* b_kv     = (const float*)d_in[18];
    const float* w_out    = (const float*)d_in[19];
    const float* b_out    = (const float*)d_in[20];
    const float* w_ogate  = (const float*)d_in[21];
    const float* b_ogate  = (const float*)d_in[22];
    float* out = (float*)d_out;

    float *p_z, *p_qkvo, *p_og, *p_wcat, *p_bcat;
    cudaGetSymbolAddress((void**)&p_z,    g_z);
    cudaGetSymbolAddress((void**)&p_qkvo, g_qkvo);
    cudaGetSymbolAddress((void**)&p_og,   g_og);
    cudaGetSymbolAddress((void**)&p_wcat, g_wcat);
    cudaGetSymbolAddress((void**)&p_bcat, g_bcat);

    // k_tri is launch #4 (ncu -s 5 -c 1 capture slot)
    k_concat<<<128, 512>>>(w_q, b_q, w_kv, b_kv, w_ogate, b_ogate);
    k_dbtab<<<TAB_N, 128>>>(w_dist, b_dist);
    k_nlr<<<NN, 32>>>(nf, w_left, b_left, w_right, b_right);
    k_tri<<<NN, 512>>>(ei, trans, w_bgate, b_bgate, w_tobias);
    k_ln<<<EE, 128>>>(ef, ln_g, ln_b);
    {
        dim3 g(EE/128, 512/128);
        k_gemm_tc<<<g, 256>>>(p_z, p_wcat, p_qkvo, 512, p_bcat, 384);
    }
    k_attn<<<NN, 128>>>();
    {
        dim3 g(EE/128, 1);
        k_gemm_tc<<<g, 256>>>(p_og, w_out, out, 128, b_out, 1 << 30);
    }
}

// round 17
// speedup vs baseline: 2.4492x; 1.0215x over previous
#include <cuda_runtime.h>
#include <cuda_bf16.h>
#include <math.h>

#define NN   768
#define KK   32
#define CS   384
#define CZ   128
#define CG   16
#define NH   4
#define EE   (NN*KK)
#define NRBF 64

// db lookup table: nearest-grid, step 0.16, 132 points, clamp at 20.8
#define TAB_H    0.16f
#define TAB_INVH 6.25f
#define TAB_N    132
#define TAB_DMAX 20.8f

typedef unsigned long long ull;
typedef unsigned int uint;

// ---- f32x2 packed helpers (sm_100+) ----
__device__ __forceinline__ ull pk2(float lo, float hi) {
    ull r; asm("mov.b64 %0, {%1,%2};" : "=l"(r) : "f"(lo), "f"(hi)); return r;
}
__device__ __forceinline__ void upk2(ull v, float& lo, float& hi) {
    asm("mov.b64 {%0,%1}, %2;" : "=f"(lo), "=f"(hi) : "l"(v));
}
__device__ __forceinline__ ull ffma2(ull a, ull b, ull c) {
    ull d; asm("fma.rn.f32x2 %0, %1, %2, %3;" : "=l"(d) : "l"(a), "l"(b), "l"(c)); return d;
}
__device__ __forceinline__ ull addf2(ull a, ull b) {
    ull d; asm("add.rn.f32x2 %0, %1, %2;" : "=l"(d) : "l"(a), "l"(b)); return d;
}
__device__ __forceinline__ float tanh_fast(float x) {
    float y; asm("tanh.approx.f32 %0, %1;" : "=f"(y) : "f"(x)); return y;
}
__device__ __forceinline__ uint bf2u(float x, float y) {
    __nv_bfloat162 h = __floats2bfloat162_rn(x, y);
    return *reinterpret_cast<uint*>(&h);
}
__device__ __forceinline__ ull shfl_xor_ull(ull v, int m) {
    uint lo = __shfl_xor_sync(0xffffffffu, (uint)v, m);
    uint hi = __shfl_xor_sync(0xffffffffu, (uint)(v >> 32), m);
    return (ull)lo | ((ull)hi << 32);
}
// ---- bf16 tensor-core mma m16n8k16 ----
__device__ __forceinline__ void mma_bf16(float& d0, float& d1, float& d2, float& d3,
                                         uint a0, uint a1, uint a2, uint a3,
                                         uint b0, uint b1) {
    asm("mma.sync.aligned.m16n8k16.row.col.f32.bf16.bf16.f32 "
        "{%0,%1,%2,%3}, {%4,%5,%6,%7}, {%8,%9}, {%0,%1,%2,%3};"
        : "+f"(d0), "+f"(d1), "+f"(d2), "+f"(d3)
        : "r"(a0), "r"(a1), "r"(a2), "r"(a3), "r"(b0), "r"(b1));
}
// ---- tf32 helpers ----
__device__ __forceinline__ uint f2tf32(float x) {
    uint u; asm("cvt.rna.tf32.f32 %0, %1;" : "=r"(u) : "f"(x)); return u;
}
__device__ __forceinline__ void mma_tf32(float& d0, float& d1, float& d2, float& d3,
                                         uint a0, uint a1, uint a2, uint a3,
                                         uint b0, uint b1) {
    asm("mma.sync.aligned.m16n8k8.row.col.f32.tf32.tf32.f32 "
        "{%0,%1,%2,%3}, {%4,%5,%6,%7}, {%8,%9}, {%0,%1,%2,%3};"
        : "+f"(d0), "+f"(d1), "+f"(d2), "+f"(d3)
        : "r"(a0), "r"(a1), "r"(a2), "r"(a3), "r"(b0), "r"(b1));
}

// ---------------- scratch (device globals; allocation-free) ----------------
__device__ float g_nl[NN*CG];
__device__ float g_nr[NN*CG];
__device__ float g_z[(size_t)EE*CZ];
__device__ float g_qkvo[(size_t)EE*512];        // q[0:128) k[128:256) v[256:384) sig(og)[384:512)
__device__ float g_bias[(size_t)NN*NH*KK*KK];   // [n][h][i][j]
__device__ float g_og[(size_t)EE*CZ];
__device__ float g_wcat[CZ*512];
__device__ float g_bcat[512];
__device__ float g_tabf[TAB_N*CZ];              // [d][c] = db(d*h, c)

// ---------------- kernel: build db lookup table (exact 64-tap sum) ----------------
__global__ void k_dbtab(const float* __restrict__ wdist, const float* __restrict__ b_dist)
{
    int d = blockIdx.x;     // 0..TAB_N-1
    int c = threadIdx.x;    // 0..127
    float dd = d * TAB_H;
    float v = b_dist[c];
    #pragma unroll 4
    for (int r = 0; r < NRBF; r++) {
        float mu = (float)r * (20.0f/63.0f);
        float w  = __ldg(wdist + r*CZ + c);
        float x = (dd - mu) * 3.2f;
        v += __expf(-x*x) * w;
    }
    g_tabf[d*CZ + c] = v;
}

// ---------------- kernel: concat projection weights ----------------
__global__ void k_concat(const float* __restrict__ wq, const float* __restrict__ bq,
                         const float* __restrict__ wkv, const float* __restrict__ bkv,
                         const float* __restrict__ wog, const float* __restrict__ bog)
{
    int c = blockIdx.x;
    int t = threadIdx.x;
    float v;
    if (t < 128)       v = wq[c*128 + t];
    else if (t < 384)  v = wkv[c*256 + (t-128)];
    else               v = wog[c*128 + (t-384)];
    g_wcat[c*512 + t] = v;
    if (c == 0) {
        float b;
        if (t < 128)      b = bq[t];
        else if (t < 384) b = bkv[t-128];
        else              b = bog[t-384];
        g_bcat[t] = b;
    }
}

// ---------------- kernel: node left/right projections ----------------
__global__ void k_nlr(const float* __restrict__ nf,
                      const float* __restrict__ wl, const float* __restrict__ bl,
                      const float* __restrict__ wr, const float* __restrict__ br)
{
    int n = blockIdx.x;
    int t = threadIdx.x;          // 32 threads
    int c0 = t & 15;
    const float* w = (t < 16) ? wl : wr;
    float acc = (t < 16) ? bl[c0] : br[c0];
    const float* row = nf + (size_t)n*CS;
    #pragma unroll 4
    for (int c = 0; c < CS; c++) acc += __ldg(row + c) * __ldg(w + c*CG + c0);
    if (t < 16) g_nl[n*CG + c0] = acc;
    else        g_nr[n*CG + c0] = acc;
}

// ---------------- kernel: LayerNorm over c_z ----------------
__global__ __launch_bounds__(128) void k_ln(const float* __restrict__ ef,
                                            const float* __restrict__ gam,
                                            const float* __restrict__ bet)
{
    int e = blockIdx.x;
    int t = threadIdx.x;
    float x = ef[(size_t)e*CZ + t];
    float s = x, s2 = x*x;
    #pragma unroll
    for (int o = 16; o > 0; o >>= 1) {
        s  += __shfl_xor_sync(0xffffffffu, s,  o);
        s2 += __shfl_xor_sync(0xffffffffu, s2, o);
    }
    __shared__ float ws[4], ws2[4];
    int w = t >> 5;
    if ((t & 31) == 0) { ws[w] = s; ws2[w] = s2; }
    __syncthreads();
    s  = ws[0]  + ws[1]  + ws[2]  + ws[3];
    s2 = ws2[0] + ws2[1] + ws2[2] + ws2[3];
    float mu  = s  * (1.f/128.f);
    float var = s2 * (1.f/128.f) - mu*mu;
    float inv = rsqrtf(var + 1e-5f);
    g_z[(size_t)e*CZ + t] = (x - mu) * inv * gam[t] + bet[t];
}

// ---------------- kernel: tf32 tensor-core GEMM ----------------
__global__ __launch_bounds__(256) void k_gemm_tc(const float* __restrict__ A,
                                                 const float* __restrict__ B,
                                                 float* __restrict__ C,
                                                 int ldb,
                                                 const float* __restrict__ bias,
                                                 int sigStart)
{
    __shared__ uint As[32*132];   // [k][m] tf32 bits
    __shared__ uint Bs[32*132];   // [k][n] tf32 bits
    int tid = threadIdx.x;
    int row0 = blockIdx.x * 128;
    int n0   = blockIdx.y * 128;
    int wid  = tid >> 5;
    int lane = tid & 31;
    int warp_m = wid >> 2;
    int warp_n = wid & 3;
    int gid = lane >> 2;
    int tig = lane & 3;
    int m0w = warp_m * 64;
    int n0w = warp_n * 32;

    float acc[4][4][4];
    #pragma unroll
    for (int mt = 0; mt < 4; mt++)
        #pragma unroll
        for (int nt = 0; nt < 4; nt++)
            #pragma unroll
            for (int q = 0; q < 4; q++) acc[mt][nt][q] = 0.f;

    for (int k0 = 0; k0 < 128; k0 += 32) {
        #pragma unroll
        for (int it = 0; it < 4; it++) {
            int idx = tid + it*256;
            int r = idx >> 3, kc = idx & 7;
            float4 v = *(const float4*)(A + (size_t)(row0 + r)*128 + k0 + kc*4);
            As[(kc*4+0)*132 + r] = f2tf32(v.x);
            As[(kc*4+1)*132 + r] = f2tf32(v.y);
            As[(kc*4+2)*132 + r] = f2tf32(v.z);
            As[(kc*4+3)*132 + r] = f2tf32(v.w);
        }
        #pragma unroll
        for (int it = 0; it < 4; it++) {
            int idx = tid + it*256;
            int r = idx >> 5, nc = idx & 31;
            float4 v = *(const float4*)(B + (size_t)(k0 + r)*ldb + n0 + nc*4);
            Bs[r*132 + nc*4 + 0] = f2tf32(v.x);
            Bs[r*132 + nc*4 + 1] = f2tf32(v.y);
            Bs[r*132 + nc*4 + 2] = f2tf32(v.z);
            Bs[r*132 + nc*4 + 3] = f2tf32(v.w);
        }
        __syncthreads();
        #pragma unroll
        for (int ks = 0; ks < 4; ks++) {
            int kb = ks * 8;
            const uint* a_lo = As + (kb + tig    )*132;
            const uint* a_hi = As + (kb + tig + 4)*132;
            uint af[4][4];
            #pragma unroll
            for (int mt = 0; mt < 4; mt++) {
                int ra = m0w + mt*16 + gid;
                af[mt][0] = a_lo[ra];
                af[mt][1] = a_lo[ra + 8];
                af[mt][2] = a_hi[ra];
                af[mt][3] = a_hi[ra + 8];
            }
            const uint* b_lo = Bs + (kb + tig    )*132;
            const uint* b_hi = Bs + (kb + tig + 4)*132;
            uint bf[4][2];
            #pragma unroll
            for (int nt = 0; nt < 4; nt++) {
                int cb = n0w + nt*8 + gid;
                bf[nt][0] = b_lo[cb];
                bf[nt][1] = b_hi[cb];
            }
            #pragma unroll
            for (int mt = 0; mt < 4; mt++)
                #pragma unroll
                for (int nt = 0; nt < 4; nt++)
                    mma_tf32(acc[mt][nt][0], acc[mt][nt][1], acc[mt][nt][2], acc[mt][nt][3],
                             af[mt][0], af[mt][1], af[mt][2], af[mt][3],
                             bf[nt][0], bf[nt][1]);
        }
        __syncthreads();
    }
    #pragma unroll
    for (int mt = 0; mt < 4; mt++) {
        int rowa = row0 + m0w + mt*16 + gid;
        #pragma unroll
        for (int nt = 0; nt < 4; nt++) {
            int col = n0 + n0w + nt*8 + 2*tig;
            float b0 = __ldg(bias + col), b1 = __ldg(bias + col + 1);
            float v0 = acc[mt][nt][0] + b0;
            float v1 = acc[mt][nt][1] + b1;
            float v2 = acc[mt][nt][2] + b0;
            float v3 = acc[mt][nt][3] + b1;
            if (col   >= sigStart) { v0 = __fdividef(1.f, 1.f + __expf(-v0));
                                     v2 = __fdividef(1.f, 1.f + __expf(-v2)); }
            if (col+1 >= sigStart) { v1 = __fdividef(1.f, 1.f + __expf(-v1));
                                     v3 = __fdividef(1.f, 1.f + __expf(-v3)); }
            float2 s0 = {v0, v1};
            float2 s1 = {v2, v3};
            *(float2*)(C + (size_t)rowa*ldb + col)     = s0;
            *(float2*)(C + (size_t)(rowa+8)*ldb + col) = s1;
        }
    }
}

// ---------------- kernel: triangle bias (tensor-core gate) ----------------
// gate[:, j, c-tile] = E1(32x16) @ M_j(16x8) via mma.m16n8k16.bf16.
// M[c][j][k] = sum_l e2[j,l] W[k*16+l, c] (phase A, f32x2 scalar math).
// s_M layout [j][c][k]: k-stride 1, c-stride 24, j-stride 386 bf16
// (193 words == 1 mod 32 -> conflict-free phase-A STS and B-frag LDS).
// db via nearest-grid f32 table. bias[h,i,j] = sum_c sigm(gate)*db*wt[c,h].
__global__ __launch_bounds__(512, 2) void k_tri(const int* __restrict__ ei,
                                                const float* __restrict__ trans,
                                                const float* __restrict__ W,       // [256,128]
                                                const float* __restrict__ b_bgate,
                                                const float* __restrict__ wtob)    // [128,4]
{
    __shared__ float          s_e2t[16*32];      // [l][j]                  2048B
    __shared__ float          s_t[32*4];         //                          512B
    __shared__ ull            s_wt2[128*2];      // [c][h-pair]             2048B
    __shared__ __nv_bfloat16  s_M[32*386 + 16];  // [j][c][k]              24736B
    __shared__ float          s_tab[TAB_N*17];   // [d][cl], stride 17      8976B
    __shared__ float          s_bg[128];         //                          512B
    __shared__ int            s_src[32];         //                          128B

    int n = blockIdx.x;
    int tid = threadIdx.x;
    int wid = tid >> 5;
    int lane = tid & 31;
    int gid = lane >> 2;        // 0..7
    int tig = lane & 3;         // 0..3

    if (tid < 32) s_src[tid] = ei[n*KK + tid];
    __syncthreads();
    {
        int i = tid >> 4, k = tid & 15;
        s_e2t[k*32 + i] = g_nr[s_src[i]*CG + k];
    }
    if (tid < 256) {
        int c = tid >> 1, p = tid & 1;
        s_wt2[c*2 + p] = pk2(wtob[c*4 + 2*p], wtob[c*4 + 2*p + 1]);
    }
    if (tid < 96) { int i = tid/3, c = tid - i*3; s_t[i*4+c] = trans[s_src[i]*3 + c]; }
    if (tid < 128) s_bg[tid] = b_bgate[tid];
    __syncthreads();

    // ---- A fragments: e1 rows, k = 2tig..2tig+1 (+8) ----
    uint af[2][4];
    #pragma unroll
    for (int t = 0; t < 2; t++) {
        int i0 = t*16 + gid, i1 = i0 + 8;
        float2 eA = *(const float2*)(g_nl + s_src[i0]*CG + 2*tig);
        float2 eB = *(const float2*)(g_nl + s_src[i1]*CG + 2*tig);
        float2 eC = *(const float2*)(g_nl + s_src[i0]*CG + 2*tig + 8);
        float2 eD = *(const float2*)(g_nl + s_src[i1]*CG + 2*tig + 8);
        af[t][0] = bf2u(eA.x, eA.y);
        af[t][1] = bf2u(eB.x, eB.y);
        af[t][2] = bf2u(eC.x, eC.y);
        af[t][3] = bf2u(eD.x, eD.y);
    }

    // ---- nearest-grid table offsets for this lane's 8 (jj, islot) positions ----
    // j = wid + 16*jj ; i = gid + 8*(islot&1) + 16*(islot>>1)
    int tabo[2][4];
    #pragma unroll
    for (int jj = 0; jj < 2; jj++) {
        int j = wid + (jj << 4);
        #pragma unroll
        for (int islot = 0; islot < 4; islot++) {
            int i = gid + ((islot & 1) << 3) + ((islot >> 1) << 4);
            float dx = s_t[i*4+0] - s_t[j*4+0] + 1e-8f;
            float dy = s_t[i*4+1] - s_t[j*4+1] + 1e-8f;
            float dz = s_t[i*4+2] - s_t[j*4+2] + 1e-8f;
            float dd = sqrtf(dx*dx + dy*dy + dz*dz);
            int idx = (int)rintf(fminf(dd, TAB_DMAX) * TAB_INVH);
            tabo[jj][islot] = idx * 17;
        }
    }

    int jA = tid & 31;          // lane (phase A)
    int kA = tid >> 5;          // warp-uniform 0..15

    ull bacc[2][4][2];
    #pragma unroll
    for (int jj = 0; jj < 2; jj++)
        #pragma unroll
        for (int s = 0; s < 4; s++) { bacc[jj][s][0] = 0ull; bacc[jj][s][1] = 0ull; }

    const uint* Mw = (const uint*)s_M;

    for (int ch = 0; ch < 8; ch++) {
        int cb = ch * 16;
        // stage table slice: s_tab[d*17 + cl] = g_tabf[d*128 + cb + cl]
        for (int p = tid; p < TAB_N*16; p += 512) {
            int d = p >> 4, cl = p & 15;
            s_tab[d*17 + cl] = __ldg(g_tabf + d*CZ + cb + cl);
        }
        // phase A: M[cloc][jA][kA] for 16 channels, two halves of 8
        #pragma unroll
        for (int half = 0; half < 2; half++) {
            ull a2[4] = {0ull, 0ull, 0ull, 0ull};
            #pragma unroll
            for (int l = 0; l < 16; l++) {
                float e2v = s_e2t[l*32 + jA];
                ull e2p = pk2(e2v, e2v);
                const ulonglong2* Wp = (const ulonglong2*)(W + (size_t)(kA*16 + l)*128 + cb + half*8);
                ulonglong2 w01 = __ldg(Wp+0), w23 = __ldg(Wp+1);
                a2[0] = ffma2(e2p, w01.x, a2[0]); a2[1] = ffma2(e2p, w01.y, a2[1]);
                a2[2] = ffma2(e2p, w23.x, a2[2]); a2[3] = ffma2(e2p, w23.y, a2[3]);
            }
            #pragma unroll
            for (int c2 = 0; c2 < 4; c2++) {
                float lo, hi;
                upk2(a2[c2], lo, hi);
                int cloc = half*8 + 2*c2;
                s_M[jA*386 + (cloc  )*24 + kA] = __float2bfloat16_rn(lo);
                s_M[jA*386 + (cloc+1)*24 + kA] = __float2bfloat16_rn(hi);
            }
        }
        __syncthreads();
        // phase B: per j, per 8-channel group: 2 mma + elementwise
        #pragma unroll
        for (int jj = 0; jj < 2; jj++) {
            int j = wid + (jj << 4);
            #pragma unroll
            for (int cg = 0; cg < 2; cg++) {
                int base = j*193 + (cg*8 + gid)*12 + tig;
                uint b0 = Mw[base], b1 = Mw[base + 4];
                float d0 = 0.f, d1 = 0.f, d2 = 0.f, d3 = 0.f;
                float d4 = 0.f, d5 = 0.f, d6 = 0.f, d7 = 0.f;
                mma_bf16(d0, d1, d2, d3, af[0][0], af[0][1], af[0][2], af[0][3], b0, b1);
                mma_bf16(d4, d5, d6, d7, af[1][0], af[1][1], af[1][2], af[1][3], b0, b1);
                int clb = cg*8 + 2*tig;                       // even local channel
                float2 bgp = *(const float2*)(s_bg + cb + clb);
                const ull* wtp = s_wt2 + (cb + clb)*2;        // c and c+1 contiguous
                ull w00 = wtp[0], w01 = wtp[1], w10 = wtp[2], w11 = wtp[3];
                float dv0[4] = {d0, d1, d2, d3};
                float dv1[4] = {d4, d5, d6, d7};
                #pragma unroll
                for (int tile = 0; tile < 2; tile++) {
                    #pragma unroll
                    for (int r = 0; r < 4; r++) {
                        int islot = (r >> 1) + (tile << 1);
                        float gv = (tile ? dv1[r] : dv0[r]) + ((r & 1) ? bgp.y : bgp.x);
                        float sg = 0.5f + 0.5f*tanh_fast(0.5f*gv);
                        float db = s_tab[tabo[jj][islot] + clb + (r & 1)];
                        float tv = sg * db;
                        ull tp = pk2(tv, tv);
                        if (r & 1) {
                            bacc[jj][islot][0] = ffma2(tp, w10, bacc[jj][islot][0]);
                            bacc[jj][islot][1] = ffma2(tp, w11, bacc[jj][islot][1]);
                        } else {
                            bacc[jj][islot][0] = ffma2(tp, w00, bacc[jj][islot][0]);
                            bacc[jj][islot][1] = ffma2(tp, w01, bacc[jj][islot][1]);
                        }
                    }
                }
            }
        }
        __syncthreads();
    }

    // ---- reduce partial bias over tig lanes, then store ----
    #pragma unroll
    for (int jj = 0; jj < 2; jj++) {
        int j = wid + (jj << 4);
        #pragma unroll
        for (int islot = 0; islot < 4; islot++) {
            ull v0 = bacc[jj][islot][0];
            ull v1 = bacc[jj][islot][1];
            v0 = addf2(v0, shfl_xor_ull(v0, 1));
            v0 = addf2(v0, shfl_xor_ull(v0, 2));
            v1 = addf2(v1, shfl_xor_ull(v1, 1));
            v1 = addf2(v1, shfl_xor_ull(v1, 2));
            if (tig == 0) {
                int i = gid + ((islot & 1) << 3) + ((islot >> 1) << 4);
                float h0, h1, h2, h3;
                upk2(v0, h0, h1);
                upk2(v1, h2, h3);
                size_t base = ((size_t)n*NH)*KK*KK + (size_t)i*KK + j;
                g_bias[base            ] = h0;
                g_bias[base +   KK*KK  ] = h1;
                g_bias[base + 2*KK*KK  ] = h2;
                g_bias[base + 3*KK*KK  ] = h3;
            }
        }
    }
}

// ---------------- kernel: attention over K neighbors, per node ----------------
__global__ __launch_bounds__(128) void k_attn()
{
    int n = blockIdx.x;
    int tid = threadIdx.x;
    int h = tid >> 5, i = tid & 31;
    __shared__ float sk[KK*CZ];
    __shared__ float sv[KK*CZ];
    for (int p = tid; p < KK*CZ; p += 128) {
        int jj = p >> 7, c = p & 127;
        size_t base = (size_t)(n*KK + jj) * 512;
        sk[p] = g_qkvo[base + 128 + c];
        sv[p] = g_qkvo[base + 256 + c];
    }
    float qr[32];
    const float scale = 0.17677669529663687f;   // 1/sqrt(32)
    size_t erow = (size_t)(n*KK + i) * 512;
    #pragma unroll
    for (int d = 0; d < 32; d++) qr[d] = g_qkvo[erow + h*32 + d] * scale;
    __syncthreads();

    float s[32];
    float mx = -1e30f;
    const float* bp = g_bias + (((size_t)n*NH + h)*KK + i)*KK;
    #pragma unroll
    for (int jj = 0; jj < 32; jj++) {
        float acc = bp[jj];
        const float* kp = sk + jj*128 + h*32;
        #pragma unroll
        for (int d = 0; d < 32; d++) acc += qr[d] * kp[d];
        s[jj] = acc;
        mx = fmaxf(mx, acc);
    }
    float sum = 0.f;
    #pragma unroll
    for (int jj = 0; jj < 32; jj++) { s[jj] = __expf(s[jj] - mx); sum += s[jj]; }
    float inv = __fdividef(1.f, sum);
    float* op = g_og + (size_t)(n*KK + i)*CZ + h*32;
    const float* ogp = g_qkvo + erow + 384 + h*32;
    #pragma unroll
    for (int d = 0; d < 32; d++) {
        float acc = 0.f;
        const float* vp = sv + h*32 + d;
        #pragma unroll
        for (int jj = 0; jj < 32; jj++) acc += s[jj] * vp[jj*128];
        op[d] = acc * inv * ogp[d];
    }
}

// ---------------- launch ----------------
extern "C" void kernel_launch(void* const* d_in, const int* in_sizes, int n_in,
                              void* d_out, int out_size)
{
    const float* nf       = (const float*)d_in[0];
    const float* trans    = (const float*)d_in[1];
    const float* ef       = (const float*)d_in[2];
    const int*   ei       = (const int*)d_in[3];
    const float* w_left   = (const float*)d_in[4];
    const float* b_left   = (const float*)d_in[5];
    const float* w_right  = (const float*)d_in[6];
    const float* b_right  = (const float*)d_in[7];
    const float* w_bgate  = (const float*)d_in[8];
    const float* b_bgate  = (const float*)d_in[9];
    const float* w_dist   = (const float*)d_in[10];
    const float* b_dist   = (const float*)d_in[11];
    const float* w_tobias = (const float*)d_in[12];
    const float* ln_g     = (const float*)d_in[13];
    const float* ln_b     = (const float*)d_in[14];
    const float* w_q      = (const float*)d_in[15];
    const float* b_q      = (const float*)d_in[16];
    const float* w_kv     = (const float*)d_in[17];
    const float* b_kv     = (const float*)d_in[18];
    const float* w_out    = (const float*)d_in[19];
    const float* b_out    = (const float*)d_in[20];
    const float* w_ogate  = (const float*)d_in[21];
    const float* b_ogate  = (const float*)d_in[22];
    float* out = (float*)d_out;

    float *p_z, *p_qkvo, *p_og, *p_wcat, *p_bcat;
    cudaGetSymbolAddress((void**)&p_z,    g_z);
    cudaGetSymbolAddress((void**)&p_qkvo, g_qkvo);
    cudaGetSymbolAddress((void**)&p_og,   g_og);
    cudaGetSymbolAddress((void**)&p_wcat, g_wcat);
    cudaGetSymbolAddress((void**)&p_bcat, g_bcat);

    // k_tri at capture slot #4
    k_concat<<<128, 512>>>(w_q, b_q, w_kv, b_kv, w_ogate, b_ogate);
    k_dbtab<<<TAB_N, 128>>>(w_dist, b_dist);
    k_nlr<<<NN, 32>>>(nf, w_left, b_left, w_right, b_right);
    k_tri<<<NN, 512>>>(ei, trans, w_bgate, b_bgate, w_tobias);
    k_ln<<<EE, 128>>>(ef, ln_g, ln_b);
    {
        dim3 g(EE/128, 512/128);
        k_gemm_tc<<<g, 256>>>(p_z, p_wcat, p_qkvo, 512, p_bcat, 384);
    }
    k_attn<<<NN, 128>>>();
    {
        dim3 g(EE/128, 1);
        k_gemm_tc<<<g, 256>>>(p_og, w_out, out, 128, b_out, 1 << 30);
    }
}